// round 11
// baseline (speedup 1.0000x reference)
#include <cuda_runtime.h>
#include <math_constants.h>

#define BN_EPS 1e-3f
#define NPTS 2048
#define NBATCH 8
#define NROWS (NPTS * NBATCH)
#define KNN 16
#define NSPLIT 2

typedef unsigned long long u64;

__device__ float g_xcat[NROWS * 512];
__device__ float g_ytb[NROWS * 512];
__device__ float g_sq[NROWS];
__device__ int   g_idx[NROWS * KNN];
__device__ float g_cv[NROWS * KNN * NSPLIT];
__device__ int   g_ci[NROWS * KNN * NSPLIT];

// ---------------- f32x2 packed helpers (FFMA2: 2x fp32 throughput) ----------
__device__ __forceinline__ void ffma2(u64& d, u64 a, u64 b) {
    asm("fma.rn.f32x2 %0, %1, %2, %0;" : "+l"(d) : "l"(a), "l"(b));
}
__device__ __forceinline__ float2 unpack2(u64 v) {
    float2 r;
    asm("mov.b64 {%0, %1}, %2;" : "=f"(r.x), "=f"(r.y) : "l"(v));
    return r;
}

// ---------------------------------------------------------------------------
__global__ void sqnorm_kernel(const float* __restrict__ x, int lda, int C,
                              float* __restrict__ sq) {
    int i = blockIdx.x * blockDim.x + threadIdx.x;
    if (i < NROWS) {
        const float* p = x + (long long)i * lda;
        float s = 0.f;
        for (int c = 0; c < C; c++) { float v = p[c]; s = fmaf(v, v, s); }
        sq[i] = s;
    }
}

// ---------------------------------------------------------------------------
__device__ __forceinline__ void topk_ins(float (&v)[16], int (&id)[16],
                                         float& vmin, int& vminid, int& minpos,
                                         float pv, int jg) {
    if (pv > vmin || (pv == vmin && jg < vminid)) {
#pragma unroll
        for (int q = 0; q < 16; q++)
            if (q == minpos) { v[q] = pv; id[q] = jg; }
        vmin = v[0]; vminid = id[0]; minpos = 0;
#pragma unroll
        for (int q = 1; q < 16; q++) {
            bool w = (v[q] < vmin) || (v[q] == vmin && id[q] > vminid);
            if (w) { vmin = v[q]; vminid = id[q]; minpos = q; }
        }
    }
}

// ---------------------------------------------------------------------------
// kNN (split, pipelined) — identical to round-10 version.
// ---------------------------------------------------------------------------
template <int C>
__global__ void knn_kernel(const float* __restrict__ x, int lda,
                           const float* __restrict__ sq,
                           float* __restrict__ outcv, int* __restrict__ outci) {
    constexpr int CC = (C < 32) ? C : 32;
    constexpr int NCHT = C / CC;
    constexpr int NREG = (64 * CC + 255) / 256;
    constexpr int NTILES = NPTS / NSPLIT / 64;
    constexpr int Q = NTILES * NCHT;
    constexpr bool EXACT = ((64 * CC) % 256) == 0;

    extern __shared__ float sm[];
    float* xiD = sm;
    float* xjT = sm + C * 136;
    float* pd  = xjT + 2 * CC * 68;

    const int rowbase = blockIdx.y * NPTS;
    const int i0 = blockIdx.x * 64;
    const int spbase = blockIdx.z * (NPTS / NSPLIT);
    const int tid = threadIdx.x;
    const int ty = tid >> 4, tx = tid & 15;
    const int srow = tid >> 2, sq4 = tid & 3;

    for (int t = tid; t < 64 * C; t += 256) {
        int i = t / C, c = t - i * C;
        float val = x[(long long)(rowbase + i0 + i) * lda + c];
        xiD[c * 136 + 2 * i] = val;
        xiD[c * 136 + 2 * i + 1] = val;
    }
    float sqi[4];
#pragma unroll
    for (int r = 0; r < 4; r++) sqi[r] = sq[rowbase + i0 + ty * 4 + r];

    float v[16]; int id[16];
#pragma unroll
    for (int q = 0; q < 16; q++) { v[q] = -CUDART_INF_F; id[q] = 0x7fffffff; }
    float vmin = -CUDART_INF_F; int vminid = 0x7fffffff; int minpos = 0;

    const float* xjp0 = xjT + tx * 4;

    float rx[NREG];
#pragma unroll
    for (int u = 0; u < NREG; u++) {
        int t = tid + u * 256;
        if (EXACT || t < 64 * CC)
            rx[u] = x[(long long)(rowbase + spbase + t / CC) * lda + t % CC];
    }
#pragma unroll
    for (int u = 0; u < NREG; u++) {
        int t = tid + u * 256;
        if (EXACT || t < 64 * CC)
            xjT[(t % CC) * 68 + t / CC] = rx[u];
    }
    __syncthreads();

    u64 acc[4][2];
#pragma unroll
    for (int r = 0; r < 4; r++) { acc[r][0] = 0ull; acc[r][1] = 0ull; }

    for (int q = 0; q < Q; q++) {
        const int ch = q % NCHT;
        const int jt = q / NCHT;
        const int j0 = spbase + jt * 64;
        const float* bufp = xjp0 + (q & 1) * CC * 68;

        if (q + 1 < Q) {
            const int njt = (q + 1) / NCHT;
            const int ncb = ((q + 1) % NCHT) * CC;
            const int nj0 = spbase + njt * 64;
#pragma unroll
            for (int u = 0; u < NREG; u++) {
                int t = tid + u * 256;
                if (EXACT || t < 64 * CC)
                    rx[u] = x[(long long)(rowbase + nj0 + t / CC) * lda + ncb + t % CC];
            }
        }

        const float* xip = xiD + (ch * CC) * 136 + ty * 8;
#pragma unroll 4
        for (int c = 0; c < CC; c++) {
            ulonglong2 a01 = *(const ulonglong2*)(xip + c * 136);
            ulonglong2 a23 = *(const ulonglong2*)(xip + c * 136 + 4);
            ulonglong2 bq  = *(const ulonglong2*)(bufp + c * 68);
            ffma2(acc[0][0], a01.x, bq.x); ffma2(acc[0][1], a01.x, bq.y);
            ffma2(acc[1][0], a01.y, bq.x); ffma2(acc[1][1], a01.y, bq.y);
            ffma2(acc[2][0], a23.x, bq.x); ffma2(acc[2][1], a23.x, bq.y);
            ffma2(acc[3][0], a23.y, bq.x); ffma2(acc[3][1], a23.y, bq.y);
        }

        if (ch == NCHT - 1) {
            float4 sj = *(const float4*)&sq[rowbase + j0 + tx * 4];
#pragma unroll
            for (int r = 0; r < 4; r++) {
                float2 lo = unpack2(acc[r][0]);
                float2 hi = unpack2(acc[r][1]);
                float4 o;
                o.x = 2.f * lo.x - sqi[r] - sj.x;
                o.y = 2.f * lo.y - sqi[r] - sj.y;
                o.z = 2.f * hi.x - sqi[r] - sj.z;
                o.w = 2.f * hi.y - sqi[r] - sj.w;
                *(float4*)&pd[(ty * 4 + r) * 68 + tx * 4] = o;
                acc[r][0] = 0ull; acc[r][1] = 0ull;
            }
        }
        __syncthreads();

        if (q + 1 < Q) {
#pragma unroll
            for (int u = 0; u < NREG; u++) {
                int t = tid + u * 256;
                if (EXACT || t < 64 * CC)
                    xjT[((q + 1) & 1) * CC * 68 + (t % CC) * 68 + t / CC] = rx[u];
            }
        }

        if (ch == NCHT - 1) {
            float tmax = -CUDART_INF_F;
#pragma unroll
            for (int s = 0; s < 4; s++) {
                const float4 pv = *(const float4*)&pd[srow * 68 + sq4 * 16 + s * 4];
                tmax = fmaxf(tmax, fmaxf(fmaxf(pv.x, pv.y), fmaxf(pv.z, pv.w)));
            }
            if (tmax >= vmin) {
#pragma unroll
                for (int s = 0; s < 4; s++) {
                    const float4 pv = *(const float4*)&pd[srow * 68 + sq4 * 16 + s * 4];
                    float m4 = fmaxf(fmaxf(pv.x, pv.y), fmaxf(pv.z, pv.w));
                    if (m4 >= vmin) {
                        int jb = j0 + sq4 * 16 + s * 4;
                        topk_ins(v, id, vmin, vminid, minpos, pv.x, jb);
                        topk_ins(v, id, vmin, vminid, minpos, pv.y, jb + 1);
                        topk_ins(v, id, vmin, vminid, minpos, pv.z, jb + 2);
                        topk_ins(v, id, vmin, vminid, minpos, pv.w, jb + 3);
                    }
                }
            }
        }
        __syncthreads();
    }

    const long long crow = (long long)(rowbase + i0 + srow) * (KNN * NSPLIT)
                           + blockIdx.z * KNN;
    for (int t = 0; t < KNN; t++) {
        float bv = -CUDART_INF_F; int bid = 0x7fffffff; int bq = 0;
#pragma unroll
        for (int q = 0; q < 16; q++) {
            bool w = (v[q] > bv) || (v[q] == bv && id[q] < bid);
            if (w) { bv = v[q]; bid = id[q]; bq = q; }
        }
        float lv = bv; int lid = bid;
#pragma unroll
        for (int off = 1; off < 4; off <<= 1) {
            float ov = __shfl_xor_sync(0xffffffffu, bv, off);
            int oid = __shfl_xor_sync(0xffffffffu, bid, off);
            if (ov > bv || (ov == bv && oid < bid)) { bv = ov; bid = oid; }
        }
        if (lid == bid && lv == bv) { v[bq] = -CUDART_INF_F; id[bq] = 0x7fffffff; }
        if (sq4 == 0) { outcv[crow + t] = bv; outci[crow + t] = bid; }
    }
}

// ---------------------------------------------------------------------------
__global__ void knnmerge_kernel(const float* __restrict__ cv, const int* __restrict__ ci,
                                int* __restrict__ outidx) {
    const int row = blockIdx.x * (blockDim.x >> 5) + (threadIdx.x >> 5);
    const int lane = threadIdx.x & 31;
    float v = cv[(long long)row * 32 + lane];
    int id = ci[(long long)row * 32 + lane];
    int rank = 0;
#pragma unroll
    for (int o = 0; o < 32; o++) {
        float ov = __shfl_sync(0xffffffffu, v, o);
        int oid = __shfl_sync(0xffffffffu, id, o);
        if (ov > v || (ov == v && oid < id)) rank++;
    }
    if (rank < KNN) outidx[(long long)row * KNN + rank] = id;
}

// ---------------------------------------------------------------------------
__global__ void sgemm_kernel(const float* __restrict__ A, int lda,
                             const float* __restrict__ W, int K, int D, int dual,
                             float* __restrict__ Co, int ldc,
                             const float* __restrict__ bg, const float* __restrict__ bb,
                             const float* __restrict__ bm, const float* __restrict__ bvv) {
    __shared__ float As[2][16 * 136];
    __shared__ float Bs[2][16 * 68];
    const int mb = blockIdx.y * 64, nb = blockIdx.x * 64;
    const int tid = threadIdx.x;
    const int ry = tid >> 4, rx = tid & 15;
    u64 acc[4][2];
#pragma unroll
    for (int r = 0; r < 4; r++) { acc[r][0] = 0ull; acc[r][1] = 0ull; }
    float ra[4], rb[4];

#pragma unroll
    for (int u = 0; u < 4; u++) {
        int t = tid + u * 256; int m = t >> 4, k = t & 15;
        ra[u] = (k < K) ? A[(long long)(mb + m) * lda + k] : 0.f;
    }
#pragma unroll
    for (int u = 0; u < 4; u++) {
        int t = tid + u * 256; int k = t >> 6, n = t & 63;
        int gn = nb + n;
        float val = 0.f;
        if (k < K) {
            if (!dual) val = W[(long long)k * D + gn];
            else if (gn < D) val = W[(long long)k * D + gn];
            else val = W[(long long)(K + k) * D + gn - D];
        }
        rb[u] = val;
    }
#pragma unroll
    for (int u = 0; u < 4; u++) {
        int t = tid + u * 256;
        As[0][(t & 15) * 136 + 2 * (t >> 4)] = ra[u];
        As[0][(t & 15) * 136 + 2 * (t >> 4) + 1] = ra[u];
        Bs[0][(t >> 6) * 68 + (t & 63)] = rb[u];
    }
    __syncthreads();

    int p = 0;
    for (int kt = 0; kt < K; kt += 16) {
        const bool more = (kt + 16 < K);
        if (more) {
#pragma unroll
            for (int u = 0; u < 4; u++) {
                int t = tid + u * 256; int m = t >> 4, k = kt + 16 + (t & 15);
                ra[u] = (k < K) ? A[(long long)(mb + m) * lda + k] : 0.f;
            }
#pragma unroll
            for (int u = 0; u < 4; u++) {
                int t = tid + u * 256; int k = kt + 16 + (t >> 6), n = t & 63;
                int gn = nb + n;
                float val = 0.f;
                if (k < K) {
                    if (!dual) val = W[(long long)k * D + gn];
                    else if (gn < D) val = W[(long long)k * D + gn];
                    else val = W[(long long)(K + k) * D + gn - D];
                }
                rb[u] = val;
            }
        }
#pragma unroll
        for (int k = 0; k < 16; k++) {
            ulonglong2 a01 = *(const ulonglong2*)&As[p][k * 136 + ry * 8];
            ulonglong2 a23 = *(const ulonglong2*)&As[p][k * 136 + ry * 8 + 4];
            ulonglong2 bq  = *(const ulonglong2*)&Bs[p][k * 68 + rx * 4];
            ffma2(acc[0][0], a01.x, bq.x); ffma2(acc[0][1], a01.x, bq.y);
            ffma2(acc[1][0], a01.y, bq.x); ffma2(acc[1][1], a01.y, bq.y);
            ffma2(acc[2][0], a23.x, bq.x); ffma2(acc[2][1], a23.x, bq.y);
            ffma2(acc[3][0], a23.y, bq.x); ffma2(acc[3][1], a23.y, bq.y);
        }
        if (more) {
            __syncthreads();
#pragma unroll
            for (int u = 0; u < 4; u++) {
                int t = tid + u * 256;
                As[p ^ 1][(t & 15) * 136 + 2 * (t >> 4)] = ra[u];
                As[p ^ 1][(t & 15) * 136 + 2 * (t >> 4) + 1] = ra[u];
                Bs[p ^ 1][(t >> 6) * 68 + (t & 63)] = rb[u];
            }
            __syncthreads();
            p ^= 1;
        }
    }

    float out[4][4];
#pragma unroll
    for (int i = 0; i < 4; i++) {
        float2 lo = unpack2(acc[i][0]);
        float2 hi = unpack2(acc[i][1]);
        out[i][0] = lo.x; out[i][1] = lo.y; out[i][2] = hi.x; out[i][3] = hi.y;
    }
    if (bg) {
#pragma unroll
        for (int j = 0; j < 4; j++) {
            int n = nb + rx * 4 + j;
            float s = bg[n] * rsqrtf(bvv[n] + BN_EPS);
            float t = bb[n] - bm[n] * s;
#pragma unroll
            for (int i = 0; i < 4; i++) out[i][j] = fmaxf(fmaf(out[i][j], s, t), 0.f);
        }
    }
#pragma unroll
    for (int i = 0; i < 4; i++) {
        *(float4*)&Co[(long long)(mb + ry * 4 + i) * ldc + nb + rx * 4] =
            make_float4(out[i][0], out[i][1], out[i][2], out[i][3]);
    }
}

// ---------------------------------------------------------------------------
__global__ void gathermax_kernel(const float* __restrict__ ytb, const int* __restrict__ idx,
                                 int D,
                                 const float* __restrict__ g, const float* __restrict__ b,
                                 const float* __restrict__ m, const float* __restrict__ vv,
                                 float* __restrict__ out, float* __restrict__ sqout) {
    const int warp = (blockIdx.x * blockDim.x + threadIdx.x) >> 5;
    const int lane = threadIdx.x & 31;
    if (warp >= NROWS) return;
    const int row = warp;
    const int base = row & ~(NPTS - 1);
    const int myid = idx[(long long)row * KNN + (lane & 15)];
    const float* top = ytb + (long long)row * 2 * D;
    float ss = 0.f;
    for (int c0 = 0; c0 < D; c0 += 64) {
        const int d = c0 + lane * 2;
        float2 g2 = *(const float2*)&g[d];
        float2 v2 = *(const float2*)&vv[d];
        float2 b2 = *(const float2*)&b[d];
        float2 m2 = *(const float2*)&m[d];
        float sx = g2.x * rsqrtf(v2.x + BN_EPS), txx = b2.x - m2.x * sx;
        float sy = g2.y * rsqrtf(v2.y + BN_EPS), tyy = b2.y - m2.y * sy;
        float2 tp = *(const float2*)&top[d];
        float bx = -CUDART_INF_F, by = -CUDART_INF_F;
#pragma unroll
        for (int k = 0; k < KNN; k++) {
            int sk = __shfl_sync(0xffffffffu, myid, k, 16);
            float2 yb = *(const float2*)&ytb[(long long)(base + sk) * 2 * D + D + d];
            bx = fmaxf(bx, fmaf(tp.x + yb.x, sx, txx));
            by = fmaxf(by, fmaf(tp.y + yb.y, sy, tyy));
        }
        bx = fmaxf(bx, 0.f); by = fmaxf(by, 0.f);
        *(float2*)&out[(long long)row * 512 + d] = make_float2(bx, by);
        ss += bx * bx + by * by;
    }
#pragma unroll
    for (int off = 16; off > 0; off >>= 1) ss += __shfl_down_sync(0xffffffffu, ss, off);
    if (lane == 0) sqout[row] = ss;
}

// ---------------------------------------------------------------------------
// MEASUREMENT ROUND: each knn stage launched TWICE (idempotent, deterministic)
// so dur_R11 - dur_R10 = total knn time. Localizes the ~2.2ms mystery.
// ---------------------------------------------------------------------------
template <int C>
static void launch_knn(const float* in, int lda, const float* sqp,
                       float* cvp, int* cip, int* idxp) {
    constexpr int CC = (C < 32) ? C : 32;
    size_t smem = (size_t)(C * 136 + 2 * CC * 68 + 64 * 68) * 4;
    static bool done = false;
    if (!done) {
        cudaFuncSetAttribute(knn_kernel<C>, cudaFuncAttributeMaxDynamicSharedMemorySize,
                             (int)smem);
        done = true;
    }
    knn_kernel<C><<<dim3(NPTS / 64, NBATCH, NSPLIT), 256, smem>>>(in, lda, sqp, cvp, cip);
    knn_kernel<C><<<dim3(NPTS / 64, NBATCH, NSPLIT), 256, smem>>>(in, lda, sqp, cvp, cip);
    knnmerge_kernel<<<NROWS / 8, 256>>>(cvp, cip, idxp);
}

extern "C" void kernel_launch(void* const* d_in, const int* in_sizes, int n_in,
                              void* d_out, int out_size) {
    const float* x = (const float*)d_in[0];
    const float *W[5], *gg[5], *bb[5], *mm[5], *vv[5];
    for (int i = 0; i < 5; i++) {
        W[i]  = (const float*)d_in[1 + 5 * i];
        gg[i] = (const float*)d_in[2 + 5 * i];
        bb[i] = (const float*)d_in[3 + 5 * i];
        mm[i] = (const float*)d_in[4 + 5 * i];
        vv[i] = (const float*)d_in[5 + 5 * i];
    }
    float *xcat, *ytb, *sqp, *cvp; int *idxp, *cip;
    cudaGetSymbolAddress((void**)&xcat, g_xcat);
    cudaGetSymbolAddress((void**)&ytb, g_ytb);
    cudaGetSymbolAddress((void**)&sqp, g_sq);
    cudaGetSymbolAddress((void**)&idxp, g_idx);
    cudaGetSymbolAddress((void**)&cvp, g_cv);
    cudaGetSymbolAddress((void**)&cip, g_ci);

    const int Cs[4] = {3, 64, 64, 128};
    const int Ds[4] = {64, 64, 128, 256};

    sqnorm_kernel<<<NROWS / 256, 256>>>(x, 3, 3, sqp);

    const float* in = x;
    int lda = 3;
    int coloff = 0;
    for (int s = 0; s < 4; s++) {
        const int C = Cs[s], D = Ds[s];
        if (C == 3)        launch_knn<3>(in, lda, sqp, cvp, cip, idxp);
        else if (C == 64)  launch_knn<64>(in, lda, sqp, cvp, cip, idxp);
        else               launch_knn<128>(in, lda, sqp, cvp, cip, idxp);
        sgemm_kernel<<<dim3(2 * D / 64, NROWS / 64), 256>>>(in, lda, W[s], C, D, 1,
                                                            ytb, 2 * D,
                                                            nullptr, nullptr, nullptr, nullptr);
        float* outp = xcat + coloff;
        gathermax_kernel<<<NROWS / 8, 256>>>(ytb, idxp, D, gg[s], bb[s], mm[s], vv[s],
                                             outp, sqp);
        in = outp; lda = 512;
        coloff += D;
    }
    sgemm_kernel<<<dim3(512 / 64, NROWS / 64), 256>>>(xcat, 512, W[4], 512, 512, 0,
                                                      (float*)d_out, 512,
                                                      gg[4], bb[4], mm[4], vv[4]);
}

// round 12
// speedup vs baseline: 2.5284x; 2.5284x over previous
#include <cuda_runtime.h>
#include <math_constants.h>

#define BN_EPS 1e-3f
#define NPTS 2048
#define NBATCH 8
#define NROWS (NPTS * NBATCH)
#define KNN 16

typedef unsigned long long u64;

__device__ float g_xcat[NROWS * 512];
__device__ float g_ytb[NROWS * 512];
__device__ float g_sq[NROWS];
__device__ int   g_idx[NROWS * KNN];
__device__ float g_pd[(long long)NROWS * NPTS];   // 134MB distance matrix

// ---------------- f32x2 packed helpers (FFMA2: 2x fp32 throughput) ----------
__device__ __forceinline__ void ffma2(u64& d, u64 a, u64 b) {
    asm("fma.rn.f32x2 %0, %1, %2, %0;" : "+l"(d) : "l"(a), "l"(b));
}
__device__ __forceinline__ float2 unpack2(u64 v) {
    float2 r;
    asm("mov.b64 {%0, %1}, %2;" : "=f"(r.x), "=f"(r.y) : "l"(v));
    return r;
}

// ---------------------------------------------------------------------------
__global__ void sqnorm_kernel(const float* __restrict__ x, int lda, int C,
                              float* __restrict__ sq) {
    int i = blockIdx.x * blockDim.x + threadIdx.x;
    if (i < NROWS) {
        const float* p = x + (long long)i * lda;
        float s = 0.f;
        for (int c = 0; c < C; c++) { float v = p[c]; s = fmaf(v, v, s); }
        sq[i] = s;
    }
}

// ---------------------------------------------------------------------------
// Phase A: pd[i, j] = 2*dot(x_i, x_j) - sq_i - sq_j for all j in i's batch.
// Pure GEMM, sgemm-proven skeleton: 64x64 tiles, 256 threads, 4x4 micro-tile
// in f32x2, double-buffered smem. Streams 64x64 fp32 tile to global.
// ---------------------------------------------------------------------------
__global__ void pdgemm_kernel(const float* __restrict__ x, int lda, int K,
                              const float* __restrict__ sq,
                              float* __restrict__ pd) {
    __shared__ float As[2][16 * 136];
    __shared__ float Bs[2][16 * 68];
    const int mb = blockIdx.y * 64;              // global i tile
    const int batch0 = (mb >> 11) << 11;         // batch row base
    const int jb = blockIdx.x * 64;              // local j tile
    const int jrow0 = batch0 + jb;               // global row of j block
    const int tid = threadIdx.x;
    const int ry = tid >> 4, rx = tid & 15;
    u64 acc[4][2];
#pragma unroll
    for (int r = 0; r < 4; r++) { acc[r][0] = 0ull; acc[r][1] = 0ull; }
    float ra[4], rb[4];

#pragma unroll
    for (int u = 0; u < 4; u++) {
        int t = tid + u * 256; int m = t >> 4, k = t & 15;
        ra[u] = (k < K) ? x[(long long)(mb + m) * lda + k] : 0.f;
    }
#pragma unroll
    for (int u = 0; u < 4; u++) {
        int t = tid + u * 256; int n = t >> 4, k = t & 15;
        rb[u] = (k < K) ? x[(long long)(jrow0 + n) * lda + k] : 0.f;
    }
#pragma unroll
    for (int u = 0; u < 4; u++) {
        int t = tid + u * 256;
        As[0][(t & 15) * 136 + 2 * (t >> 4)] = ra[u];
        As[0][(t & 15) * 136 + 2 * (t >> 4) + 1] = ra[u];
        Bs[0][(t & 15) * 68 + (t >> 4)] = rb[u];
    }
    __syncthreads();

    int p = 0;
    for (int kt = 0; kt < K; kt += 16) {
        const bool more = (kt + 16 < K);
        if (more) {
#pragma unroll
            for (int u = 0; u < 4; u++) {
                int t = tid + u * 256; int m = t >> 4, k = kt + 16 + (t & 15);
                ra[u] = (k < K) ? x[(long long)(mb + m) * lda + k] : 0.f;
            }
#pragma unroll
            for (int u = 0; u < 4; u++) {
                int t = tid + u * 256; int n = t >> 4, k = kt + 16 + (t & 15);
                rb[u] = (k < K) ? x[(long long)(jrow0 + n) * lda + k] : 0.f;
            }
        }
#pragma unroll
        for (int k = 0; k < 16; k++) {
            ulonglong2 a01 = *(const ulonglong2*)&As[p][k * 136 + ry * 8];
            ulonglong2 a23 = *(const ulonglong2*)&As[p][k * 136 + ry * 8 + 4];
            ulonglong2 bq  = *(const ulonglong2*)&Bs[p][k * 68 + rx * 4];
            ffma2(acc[0][0], a01.x, bq.x); ffma2(acc[0][1], a01.x, bq.y);
            ffma2(acc[1][0], a01.y, bq.x); ffma2(acc[1][1], a01.y, bq.y);
            ffma2(acc[2][0], a23.x, bq.x); ffma2(acc[2][1], a23.x, bq.y);
            ffma2(acc[3][0], a23.y, bq.x); ffma2(acc[3][1], a23.y, bq.y);
        }
        if (more) {
            __syncthreads();
#pragma unroll
            for (int u = 0; u < 4; u++) {
                int t = tid + u * 256;
                As[p ^ 1][(t & 15) * 136 + 2 * (t >> 4)] = ra[u];
                As[p ^ 1][(t & 15) * 136 + 2 * (t >> 4) + 1] = ra[u];
                Bs[p ^ 1][(t & 15) * 68 + (t >> 4)] = rb[u];
            }
            __syncthreads();
            p ^= 1;
        }
    }

    // epilogue: 2*acc - sqi - sqj -> global pd
    float4 sj = *(const float4*)&sq[jrow0 + rx * 4];
#pragma unroll
    for (int i = 0; i < 4; i++) {
        float sqi = sq[mb + ry * 4 + i];
        float2 lo = unpack2(acc[i][0]);
        float2 hi = unpack2(acc[i][1]);
        float4 o;
        o.x = 2.f * lo.x - sqi - sj.x;
        o.y = 2.f * lo.y - sqi - sj.y;
        o.z = 2.f * hi.x - sqi - sj.z;
        o.w = 2.f * hi.y - sqi - sj.w;
        *(float4*)&pd[(long long)(mb + ry * 4 + i) * NPTS + jb + rx * 4] = o;
    }
}

// ---------------------------------------------------------------------------
// Phase B: exact top-16 per row by iterative max-extraction. Warp per row.
// Row cached in smem (8KB/warp); lane owns j = lane (mod 32) strided elems.
// Ties -> lower index (matches jax.lax.top_k). Output in descending order.
// ---------------------------------------------------------------------------
__global__ void topk_kernel(const float* __restrict__ pd, int* __restrict__ outidx) {
    extern __shared__ float rows[];                 // 8 warps x 2048 floats
    const int warp = threadIdx.x >> 5, lane = threadIdx.x & 31;
    const long long row = (long long)blockIdx.x * 8 + warp;
    float* rb = rows + warp * 2048;
    const float4* src = (const float4*)(pd + row * NPTS);
#pragma unroll
    for (int i = 0; i < 16; i++)
        ((float4*)rb)[lane + i * 32] = src[lane + i * 32];
    __syncwarp();

    // lane-local best over its 64 strided elements (ascending j: strict >
    // keeps lowest index on ties)
    float bestv = -CUDART_INF_F; int besti = 0;
#pragma unroll 8
    for (int s = 0; s < 64; s++) {
        float pv = rb[lane + 32 * s];
        if (pv > bestv) { bestv = pv; besti = lane + 32 * s; }
    }

    for (int t = 0; t < KNN; t++) {
        float wv = bestv; int wi = besti;
#pragma unroll
        for (int off = 16; off > 0; off >>= 1) {
            float ov = __shfl_xor_sync(0xffffffffu, wv, off);
            int oi = __shfl_xor_sync(0xffffffffu, wi, off);
            if (ov > wv || (ov == wv && oi < wi)) { wv = ov; wi = oi; }
        }
        if (lane == 0) outidx[row * KNN + t] = wi;
        if (besti == wi) {        // unique winner lane removes + rescans
            rb[wi] = -CUDART_INF_F;
            bestv = -CUDART_INF_F; besti = 0;
#pragma unroll 8
            for (int s = 0; s < 64; s++) {
                float pv = rb[lane + 32 * s];
                if (pv > bestv) { bestv = pv; besti = lane + 32 * s; }
            }
        }
    }
}

// ---------------------------------------------------------------------------
// SGEMM 64x64x16, 256 threads, 4x4 micro-tile in f32x2, double-buffered.
// dual: out [rows,2D] = A @ [Wtop|Wbot]. Optional fused BN+ReLU.
// ---------------------------------------------------------------------------
__global__ void sgemm_kernel(const float* __restrict__ A, int lda,
                             const float* __restrict__ W, int K, int D, int dual,
                             float* __restrict__ Co, int ldc,
                             const float* __restrict__ bg, const float* __restrict__ bb,
                             const float* __restrict__ bm, const float* __restrict__ bvv) {
    __shared__ float As[2][16 * 136];
    __shared__ float Bs[2][16 * 68];
    const int mb = blockIdx.y * 64, nb = blockIdx.x * 64;
    const int tid = threadIdx.x;
    const int ry = tid >> 4, rx = tid & 15;
    u64 acc[4][2];
#pragma unroll
    for (int r = 0; r < 4; r++) { acc[r][0] = 0ull; acc[r][1] = 0ull; }
    float ra[4], rb[4];

#pragma unroll
    for (int u = 0; u < 4; u++) {
        int t = tid + u * 256; int m = t >> 4, k = t & 15;
        ra[u] = (k < K) ? A[(long long)(mb + m) * lda + k] : 0.f;
    }
#pragma unroll
    for (int u = 0; u < 4; u++) {
        int t = tid + u * 256; int k = t >> 6, n = t & 63;
        int gn = nb + n;
        float val = 0.f;
        if (k < K) {
            if (!dual) val = W[(long long)k * D + gn];
            else if (gn < D) val = W[(long long)k * D + gn];
            else val = W[(long long)(K + k) * D + gn - D];
        }
        rb[u] = val;
    }
#pragma unroll
    for (int u = 0; u < 4; u++) {
        int t = tid + u * 256;
        As[0][(t & 15) * 136 + 2 * (t >> 4)] = ra[u];
        As[0][(t & 15) * 136 + 2 * (t >> 4) + 1] = ra[u];
        Bs[0][(t >> 6) * 68 + (t & 63)] = rb[u];
    }
    __syncthreads();

    int p = 0;
    for (int kt = 0; kt < K; kt += 16) {
        const bool more = (kt + 16 < K);
        if (more) {
#pragma unroll
            for (int u = 0; u < 4; u++) {
                int t = tid + u * 256; int m = t >> 4, k = kt + 16 + (t & 15);
                ra[u] = (k < K) ? A[(long long)(mb + m) * lda + k] : 0.f;
            }
#pragma unroll
            for (int u = 0; u < 4; u++) {
                int t = tid + u * 256; int k = kt + 16 + (t >> 6), n = t & 63;
                int gn = nb + n;
                float val = 0.f;
                if (k < K) {
                    if (!dual) val = W[(long long)k * D + gn];
                    else if (gn < D) val = W[(long long)k * D + gn];
                    else val = W[(long long)(K + k) * D + gn - D];
                }
                rb[u] = val;
            }
        }
#pragma unroll
        for (int k = 0; k < 16; k++) {
            ulonglong2 a01 = *(const ulonglong2*)&As[p][k * 136 + ry * 8];
            ulonglong2 a23 = *(const ulonglong2*)&As[p][k * 136 + ry * 8 + 4];
            ulonglong2 bq  = *(const ulonglong2*)&Bs[p][k * 68 + rx * 4];
            ffma2(acc[0][0], a01.x, bq.x); ffma2(acc[0][1], a01.x, bq.y);
            ffma2(acc[1][0], a01.y, bq.x); ffma2(acc[1][1], a01.y, bq.y);
            ffma2(acc[2][0], a23.x, bq.x); ffma2(acc[2][1], a23.x, bq.y);
            ffma2(acc[3][0], a23.y, bq.x); ffma2(acc[3][1], a23.y, bq.y);
        }
        if (more) {
            __syncthreads();
#pragma unroll
            for (int u = 0; u < 4; u++) {
                int t = tid + u * 256;
                As[p ^ 1][(t & 15) * 136 + 2 * (t >> 4)] = ra[u];
                As[p ^ 1][(t & 15) * 136 + 2 * (t >> 4) + 1] = ra[u];
                Bs[p ^ 1][(t >> 6) * 68 + (t & 63)] = rb[u];
            }
            __syncthreads();
            p ^= 1;
        }
    }

    float out[4][4];
#pragma unroll
    for (int i = 0; i < 4; i++) {
        float2 lo = unpack2(acc[i][0]);
        float2 hi = unpack2(acc[i][1]);
        out[i][0] = lo.x; out[i][1] = lo.y; out[i][2] = hi.x; out[i][3] = hi.y;
    }
    if (bg) {
#pragma unroll
        for (int j = 0; j < 4; j++) {
            int n = nb + rx * 4 + j;
            float s = bg[n] * rsqrtf(bvv[n] + BN_EPS);
            float t = bb[n] - bm[n] * s;
#pragma unroll
            for (int i = 0; i < 4; i++) out[i][j] = fmaxf(fmaf(out[i][j], s, t), 0.f);
        }
    }
#pragma unroll
    for (int i = 0; i < 4; i++) {
        *(float4*)&Co[(long long)(mb + ry * 4 + i) * ldc + nb + rx * 4] =
            make_float4(out[i][0], out[i][1], out[i][2], out[i][3]);
    }
}

// ---------------------------------------------------------------------------
// gather + BN + ReLU + max over k=16; fused next-stage sqnorm. Warp per row.
// ---------------------------------------------------------------------------
__global__ void gathermax_kernel(const float* __restrict__ ytb, const int* __restrict__ idx,
                                 int D,
                                 const float* __restrict__ g, const float* __restrict__ b,
                                 const float* __restrict__ m, const float* __restrict__ vv,
                                 float* __restrict__ out, float* __restrict__ sqout) {
    const int warp = (blockIdx.x * blockDim.x + threadIdx.x) >> 5;
    const int lane = threadIdx.x & 31;
    if (warp >= NROWS) return;
    const int row = warp;
    const int base = row & ~(NPTS - 1);
    const int myid = idx[(long long)row * KNN + (lane & 15)];
    const float* top = ytb + (long long)row * 2 * D;
    float ss = 0.f;
    for (int c0 = 0; c0 < D; c0 += 64) {
        const int d = c0 + lane * 2;
        float2 g2 = *(const float2*)&g[d];
        float2 v2 = *(const float2*)&vv[d];
        float2 b2 = *(const float2*)&b[d];
        float2 m2 = *(const float2*)&m[d];
        float sx = g2.x * rsqrtf(v2.x + BN_EPS), txx = b2.x - m2.x * sx;
        float sy = g2.y * rsqrtf(v2.y + BN_EPS), tyy = b2.y - m2.y * sy;
        float2 tp = *(const float2*)&top[d];
        float bx = -CUDART_INF_F, by = -CUDART_INF_F;
#pragma unroll
        for (int k = 0; k < KNN; k++) {
            int sk = __shfl_sync(0xffffffffu, myid, k, 16);
            float2 yb = *(const float2*)&ytb[(long long)(base + sk) * 2 * D + D + d];
            bx = fmaxf(bx, fmaf(tp.x + yb.x, sx, txx));
            by = fmaxf(by, fmaf(tp.y + yb.y, sy, tyy));
        }
        bx = fmaxf(bx, 0.f); by = fmaxf(by, 0.f);
        *(float2*)&out[(long long)row * 512 + d] = make_float2(bx, by);
        ss += bx * bx + by * by;
    }
#pragma unroll
    for (int off = 16; off > 0; off >>= 1) ss += __shfl_down_sync(0xffffffffu, ss, off);
    if (lane == 0) sqout[row] = ss;
}

// ---------------------------------------------------------------------------
extern "C" void kernel_launch(void* const* d_in, const int* in_sizes, int n_in,
                              void* d_out, int out_size) {
    const float* x = (const float*)d_in[0];
    const float *W[5], *gg[5], *bb[5], *mm[5], *vv[5];
    for (int i = 0; i < 5; i++) {
        W[i]  = (const float*)d_in[1 + 5 * i];
        gg[i] = (const float*)d_in[2 + 5 * i];
        bb[i] = (const float*)d_in[3 + 5 * i];
        mm[i] = (const float*)d_in[4 + 5 * i];
        vv[i] = (const float*)d_in[5 + 5 * i];
    }
    float *xcat, *ytb, *sqp, *pdp; int* idxp;
    cudaGetSymbolAddress((void**)&xcat, g_xcat);
    cudaGetSymbolAddress((void**)&ytb, g_ytb);
    cudaGetSymbolAddress((void**)&sqp, g_sq);
    cudaGetSymbolAddress((void**)&idxp, g_idx);
    cudaGetSymbolAddress((void**)&pdp, g_pd);

    static bool tinit = false;
    if (!tinit) {
        cudaFuncSetAttribute(topk_kernel, cudaFuncAttributeMaxDynamicSharedMemorySize,
                             8 * 2048 * 4);
        tinit = true;
    }

    const int Cs[4] = {3, 64, 64, 128};
    const int Ds[4] = {64, 64, 128, 256};

    sqnorm_kernel<<<NROWS / 256, 256>>>(x, 3, 3, sqp);

    const float* in = x;
    int lda = 3;
    int coloff = 0;
    for (int s = 0; s < 4; s++) {
        const int C = Cs[s], D = Ds[s];
        pdgemm_kernel<<<dim3(NPTS / 64, NROWS / 64), 256>>>(in, lda, C, sqp, pdp);
        topk_kernel<<<NROWS / 8, 256, 8 * 2048 * 4>>>(pdp, idxp);
        sgemm_kernel<<<dim3(2 * D / 64, NROWS / 64), 256>>>(in, lda, W[s], C, D, 1,
                                                            ytb, 2 * D,
                                                            nullptr, nullptr, nullptr, nullptr);
        float* outp = xcat + coloff;
        gathermax_kernel<<<NROWS / 8, 256>>>(ytb, idxp, D, gg[s], bb[s], mm[s], vv[s],
                                             outp, sqp);
        in = outp; lda = 512;
        coloff += D;
    }
    sgemm_kernel<<<dim3(512 / 64, NROWS / 64), 256>>>(xcat, 512, W[4], 512, 512, 0,
                                                      (float*)d_out, 512,
                                                      gg[4], bb[4], mm[4], vv[4]);
}

// round 13
// speedup vs baseline: 2.9513x; 1.1673x over previous
#include <cuda_runtime.h>
#include <math_constants.h>

#define BN_EPS 1e-3f
#define NPTS 2048
#define NBATCH 8
#define NROWS (NPTS * NBATCH)
#define KNN 16

typedef unsigned long long u64;

__device__ float g_xcat[NROWS * 512];
__device__ float g_ytb[NROWS * 512];
__device__ float g_sq[NROWS];
__device__ int   g_idx[NROWS * KNN];
__device__ float g_pd[(long long)NROWS * NPTS];   // 134MB distance matrix

// ---------------- f32x2 packed helpers (FFMA2: 2x fp32 throughput) ----------
__device__ __forceinline__ void ffma2(u64& d, u64 a, u64 b) {
    asm("fma.rn.f32x2 %0, %1, %2, %0;" : "+l"(d) : "l"(a), "l"(b));
}
__device__ __forceinline__ float2 unpack2(u64 v) {
    float2 r;
    asm("mov.b64 {%0, %1}, %2;" : "=f"(r.x), "=f"(r.y) : "l"(v));
    return r;
}

// ---------------------------------------------------------------------------
__global__ void sqnorm_kernel(const float* __restrict__ x, int lda, int C,
                              float* __restrict__ sq) {
    int i = blockIdx.x * blockDim.x + threadIdx.x;
    if (i < NROWS) {
        const float* p = x + (long long)i * lda;
        float s = 0.f;
        for (int c = 0; c < C; c++) { float v = p[c]; s = fmaf(v, v, s); }
        sq[i] = s;
    }
}

// ---------------------------------------------------------------------------
// Phase A: pd[i, j] = 2*dot(x_i, x_j) - sq_i - sq_j. Pure GEMM.
// 128x64 tiles, 256 threads (16x16), 8x4 micro-tile in f32x2 (acc = 32 regs).
// Double-buffered smem; A stored duplicated for LDS.128 (v,v) pairs.
// ---------------------------------------------------------------------------
__global__ void pdgemm_kernel(const float* __restrict__ x, int lda, int K,
                              const float* __restrict__ sq,
                              float* __restrict__ pd) {
    __shared__ float As[2][16 * 264];
    __shared__ float Bs[2][16 * 68];
    const int mb = blockIdx.y * 128;             // global i tile (within batch)
    const int batch0 = (mb >> 11) << 11;         // batch row base
    const int jb = blockIdx.x * 64;              // local j tile
    const int jrow0 = batch0 + jb;
    const int tid = threadIdx.x;
    const int ty = tid >> 4, tx = tid & 15;
    u64 acc[8][2];
#pragma unroll
    for (int r = 0; r < 8; r++) { acc[r][0] = 0ull; acc[r][1] = 0ull; }
    float ra[8], rb[4];

#pragma unroll
    for (int u = 0; u < 8; u++) {
        int t = tid + u * 256; int m = t >> 4, k = t & 15;
        ra[u] = (k < K) ? x[(long long)(mb + m) * lda + k] : 0.f;
    }
#pragma unroll
    for (int u = 0; u < 4; u++) {
        int t = tid + u * 256; int n = t >> 4, k = t & 15;
        rb[u] = (k < K) ? x[(long long)(jrow0 + n) * lda + k] : 0.f;
    }
#pragma unroll
    for (int u = 0; u < 8; u++) {
        int t = tid + u * 256;
        As[0][(t & 15) * 264 + 2 * (t >> 4)] = ra[u];
        As[0][(t & 15) * 264 + 2 * (t >> 4) + 1] = ra[u];
    }
#pragma unroll
    for (int u = 0; u < 4; u++) {
        int t = tid + u * 256;
        Bs[0][(t & 15) * 68 + (t >> 4)] = rb[u];
    }
    __syncthreads();

    int p = 0;
    for (int kt = 0; kt < K; kt += 16) {
        const bool more = (kt + 16 < K);
        if (more) {
#pragma unroll
            for (int u = 0; u < 8; u++) {
                int t = tid + u * 256; int m = t >> 4, k = kt + 16 + (t & 15);
                ra[u] = (k < K) ? x[(long long)(mb + m) * lda + k] : 0.f;
            }
#pragma unroll
            for (int u = 0; u < 4; u++) {
                int t = tid + u * 256; int n = t >> 4, k = kt + 16 + (t & 15);
                rb[u] = (k < K) ? x[(long long)(jrow0 + n) * lda + k] : 0.f;
            }
        }
        const float* ap = &As[p][ty * 16];
        const float* bp = &Bs[p][tx * 4];
#pragma unroll
        for (int k = 0; k < 16; k++) {
            ulonglong2 a01 = *(const ulonglong2*)(ap + k * 264);
            ulonglong2 a23 = *(const ulonglong2*)(ap + k * 264 + 4);
            ulonglong2 a45 = *(const ulonglong2*)(ap + k * 264 + 8);
            ulonglong2 a67 = *(const ulonglong2*)(ap + k * 264 + 12);
            ulonglong2 bq  = *(const ulonglong2*)(bp + k * 68);
            ffma2(acc[0][0], a01.x, bq.x); ffma2(acc[0][1], a01.x, bq.y);
            ffma2(acc[1][0], a01.y, bq.x); ffma2(acc[1][1], a01.y, bq.y);
            ffma2(acc[2][0], a23.x, bq.x); ffma2(acc[2][1], a23.x, bq.y);
            ffma2(acc[3][0], a23.y, bq.x); ffma2(acc[3][1], a23.y, bq.y);
            ffma2(acc[4][0], a45.x, bq.x); ffma2(acc[4][1], a45.x, bq.y);
            ffma2(acc[5][0], a45.y, bq.x); ffma2(acc[5][1], a45.y, bq.y);
            ffma2(acc[6][0], a67.x, bq.x); ffma2(acc[6][1], a67.x, bq.y);
            ffma2(acc[7][0], a67.y, bq.x); ffma2(acc[7][1], a67.y, bq.y);
        }
        if (more) {
            __syncthreads();
#pragma unroll
            for (int u = 0; u < 8; u++) {
                int t = tid + u * 256;
                As[p ^ 1][(t & 15) * 264 + 2 * (t >> 4)] = ra[u];
                As[p ^ 1][(t & 15) * 264 + 2 * (t >> 4) + 1] = ra[u];
            }
#pragma unroll
            for (int u = 0; u < 4; u++) {
                int t = tid + u * 256;
                Bs[p ^ 1][(t & 15) * 68 + (t >> 4)] = rb[u];
            }
            __syncthreads();
            p ^= 1;
        }
    }

    // epilogue: 2*acc - sqi - sqj -> global pd
    float4 sj = *(const float4*)&sq[jrow0 + tx * 4];
#pragma unroll
    for (int i = 0; i < 8; i++) {
        float sqi = sq[mb + ty * 8 + i];
        float2 lo = unpack2(acc[i][0]);
        float2 hi = unpack2(acc[i][1]);
        float4 o;
        o.x = 2.f * lo.x - sqi - sj.x;
        o.y = 2.f * lo.y - sqi - sj.y;
        o.z = 2.f * hi.x - sqi - sj.z;
        o.w = 2.f * hi.y - sqi - sj.w;
        *(float4*)&pd[(long long)(mb + ty * 8 + i) * NPTS + jb + tx * 4] = o;
    }
}

// ---------------------------------------------------------------------------
// Phase B: exact top-16 per row, warp per row, per-lane TOP-2 tracking so the
// serial rescan only fires when a lane's second is exhausted.
// Ties -> lower index (matches jax.lax.top_k).
// ---------------------------------------------------------------------------
__global__ void topk_kernel(const float* __restrict__ pd, int* __restrict__ outidx) {
    extern __shared__ float rows[];                 // 8 warps x 2048 floats
    const int warp = threadIdx.x >> 5, lane = threadIdx.x & 31;
    const long long row = (long long)blockIdx.x * 8 + warp;
    float* rb = rows + warp * 2048;
    const float4* src = (const float4*)(pd + row * NPTS);
#pragma unroll
    for (int i = 0; i < 16; i++)
        ((float4*)rb)[lane + i * 32] = src[lane + i * 32];
    __syncwarp();

    // per-lane top-2 over its 64 strided elements (ascending: strict > keeps
    // lowest index; equal-to-best falls through to second with higher index)
    float bestv = -CUDART_INF_F, secondv = -CUDART_INF_F;
    int besti = 0x7fffffff, seci = -1;
#pragma unroll 8
    for (int s = 0; s < 64; s++) {
        float pv = rb[lane + 32 * s];
        int ix = lane + 32 * s;
        if (pv > bestv) {
            secondv = bestv; seci = besti;
            bestv = pv; besti = ix;
        } else if (pv > secondv) {
            secondv = pv; seci = ix;
        }
    }

    for (int t = 0; t < KNN; t++) {
        float wv = bestv; int wi = besti;
#pragma unroll
        for (int off = 16; off > 0; off >>= 1) {
            float ov = __shfl_xor_sync(0xffffffffu, wv, off);
            int oi = __shfl_xor_sync(0xffffffffu, wi, off);
            if (ov > wv || (ov == wv && oi < wi)) { wv = ov; wi = oi; }
        }
        if (lane == 0) outidx[row * KNN + t] = wi;
        if (besti == wi) {                 // unique winner lane
            rb[wi] = -CUDART_INF_F;
            if (seci >= 0) {               // promote second
                bestv = secondv; besti = seci;
                secondv = -CUDART_INF_F; seci = -1;
            } else {                       // rare: rescan top-2
                bestv = -CUDART_INF_F; secondv = -CUDART_INF_F;
                besti = 0x7fffffff; seci = -1;
#pragma unroll 8
                for (int s = 0; s < 64; s++) {
                    float pv = rb[lane + 32 * s];
                    int ix = lane + 32 * s;
                    if (pv > bestv) {
                        secondv = bestv; seci = besti;
                        bestv = pv; besti = ix;
                    } else if (pv > secondv) {
                        secondv = pv; seci = ix;
                    }
                }
            }
        }
    }
}

// ---------------------------------------------------------------------------
// SGEMM 128x64x16, 256 threads, 8x4 micro-tile in f32x2, double-buffered.
// dual: out [rows,2D] = A @ [Wtop|Wbot]. Optional fused BN+ReLU.
// ---------------------------------------------------------------------------
__global__ void sgemm_kernel(const float* __restrict__ A, int lda,
                             const float* __restrict__ W, int K, int D, int dual,
                             float* __restrict__ Co, int ldc,
                             const float* __restrict__ bg, const float* __restrict__ bb,
                             const float* __restrict__ bm, const float* __restrict__ bvv) {
    __shared__ float As[2][16 * 264];
    __shared__ float Bs[2][16 * 68];
    const int mb = blockIdx.y * 128, nb = blockIdx.x * 64;
    const int tid = threadIdx.x;
    const int ty = tid >> 4, tx = tid & 15;
    u64 acc[8][2];
#pragma unroll
    for (int r = 0; r < 8; r++) { acc[r][0] = 0ull; acc[r][1] = 0ull; }
    float ra[8], rb[4];

#pragma unroll
    for (int u = 0; u < 8; u++) {
        int t = tid + u * 256; int m = t >> 4, k = t & 15;
        ra[u] = (k < K) ? A[(long long)(mb + m) * lda + k] : 0.f;
    }
#pragma unroll
    for (int u = 0; u < 4; u++) {
        int t = tid + u * 256; int k = t >> 6, n = t & 63;
        int gn = nb + n;
        float val = 0.f;
        if (k < K) {
            if (!dual) val = W[(long long)k * D + gn];
            else if (gn < D) val = W[(long long)k * D + gn];
            else val = W[(long long)(K + k) * D + gn - D];
        }
        rb[u] = val;
    }
#pragma unroll
    for (int u = 0; u < 8; u++) {
        int t = tid + u * 256;
        As[0][(t & 15) * 264 + 2 * (t >> 4)] = ra[u];
        As[0][(t & 15) * 264 + 2 * (t >> 4) + 1] = ra[u];
    }
#pragma unroll
    for (int u = 0; u < 4; u++) {
        int t = tid + u * 256;
        Bs[0][(t >> 6) * 68 + (t & 63)] = rb[u];
    }
    __syncthreads();

    int p = 0;
    for (int kt = 0; kt < K; kt += 16) {
        const bool more = (kt + 16 < K);
        if (more) {
#pragma unroll
            for (int u = 0; u < 8; u++) {
                int t = tid + u * 256; int m = t >> 4, k = kt + 16 + (t & 15);
                ra[u] = (k < K) ? A[(long long)(mb + m) * lda + k] : 0.f;
            }
#pragma unroll
            for (int u = 0; u < 4; u++) {
                int t = tid + u * 256; int k = kt + 16 + (t >> 6), n = t & 63;
                int gn = nb + n;
                float val = 0.f;
                if (k < K) {
                    if (!dual) val = W[(long long)k * D + gn];
                    else if (gn < D) val = W[(long long)k * D + gn];
                    else val = W[(long long)(K + k) * D + gn - D];
                }
                rb[u] = val;
            }
        }
        const float* ap = &As[p][ty * 16];
        const float* bp = &Bs[p][tx * 4];
#pragma unroll
        for (int k = 0; k < 16; k++) {
            ulonglong2 a01 = *(const ulonglong2*)(ap + k * 264);
            ulonglong2 a23 = *(const ulonglong2*)(ap + k * 264 + 4);
            ulonglong2 a45 = *(const ulonglong2*)(ap + k * 264 + 8);
            ulonglong2 a67 = *(const ulonglong2*)(ap + k * 264 + 12);
            ulonglong2 bq  = *(const ulonglong2*)(bp + k * 68);
            ffma2(acc[0][0], a01.x, bq.x); ffma2(acc[0][1], a01.x, bq.y);
            ffma2(acc[1][0], a01.y, bq.x); ffma2(acc[1][1], a01.y, bq.y);
            ffma2(acc[2][0], a23.x, bq.x); ffma2(acc[2][1], a23.x, bq.y);
            ffma2(acc[3][0], a23.y, bq.x); ffma2(acc[3][1], a23.y, bq.y);
            ffma2(acc[4][0], a45.x, bq.x); ffma2(acc[4][1], a45.x, bq.y);
            ffma2(acc[5][0], a45.y, bq.x); ffma2(acc[5][1], a45.y, bq.y);
            ffma2(acc[6][0], a67.x, bq.x); ffma2(acc[6][1], a67.x, bq.y);
            ffma2(acc[7][0], a67.y, bq.x); ffma2(acc[7][1], a67.y, bq.y);
        }
        if (more) {
            __syncthreads();
#pragma unroll
            for (int u = 0; u < 8; u++) {
                int t = tid + u * 256;
                As[p ^ 1][(t & 15) * 264 + 2 * (t >> 4)] = ra[u];
                As[p ^ 1][(t & 15) * 264 + 2 * (t >> 4) + 1] = ra[u];
            }
#pragma unroll
            for (int u = 0; u < 4; u++) {
                int t = tid + u * 256;
                Bs[p ^ 1][(t >> 6) * 68 + (t & 63)] = rb[u];
            }
            __syncthreads();
            p ^= 1;
        }
    }

    // epilogue: optional BN+ReLU per column, then store
    float s4[4], t4[4];
    if (bg) {
#pragma unroll
        for (int j = 0; j < 4; j++) {
            int n = nb + tx * 4 + j;
            s4[j] = bg[n] * rsqrtf(bvv[n] + BN_EPS);
            t4[j] = bb[n] - bm[n] * s4[j];
        }
    }
#pragma unroll
    for (int i = 0; i < 8; i++) {
        float2 lo = unpack2(acc[i][0]);
        float2 hi = unpack2(acc[i][1]);
        float o[4] = {lo.x, lo.y, hi.x, hi.y};
        if (bg) {
#pragma unroll
            for (int j = 0; j < 4; j++)
                o[j] = fmaxf(fmaf(o[j], s4[j], t4[j]), 0.f);
        }
        *(float4*)&Co[(long long)(mb + ty * 8 + i) * ldc + nb + tx * 4] =
            make_float4(o[0], o[1], o[2], o[3]);
    }
}

// ---------------------------------------------------------------------------
// gather + BN + ReLU + max over k=16; fused next-stage sqnorm. Warp per row.
// ---------------------------------------------------------------------------
__global__ void gathermax_kernel(const float* __restrict__ ytb, const int* __restrict__ idx,
                                 int D,
                                 const float* __restrict__ g, const float* __restrict__ b,
                                 const float* __restrict__ m, const float* __restrict__ vv,
                                 float* __restrict__ out, float* __restrict__ sqout) {
    const int warp = (blockIdx.x * blockDim.x + threadIdx.x) >> 5;
    const int lane = threadIdx.x & 31;
    if (warp >= NROWS) return;
    const int row = warp;
    const int base = row & ~(NPTS - 1);
    const int myid = idx[(long long)row * KNN + (lane & 15)];
    const float* top = ytb + (long long)row * 2 * D;
    float ss = 0.f;
    for (int c0 = 0; c0 < D; c0 += 64) {
        const int d = c0 + lane * 2;
        float2 g2 = *(const float2*)&g[d];
        float2 v2 = *(const float2*)&vv[d];
        float2 b2 = *(const float2*)&b[d];
        float2 m2 = *(const float2*)&m[d];
        float sx = g2.x * rsqrtf(v2.x + BN_EPS), txx = b2.x - m2.x * sx;
        float sy = g2.y * rsqrtf(v2.y + BN_EPS), tyy = b2.y - m2.y * sy;
        float2 tp = *(const float2*)&top[d];
        float bx = -CUDART_INF_F, by = -CUDART_INF_F;
#pragma unroll
        for (int k = 0; k < KNN; k++) {
            int sk = __shfl_sync(0xffffffffu, myid, k, 16);
            float2 yb = *(const float2*)&ytb[(long long)(base + sk) * 2 * D + D + d];
            bx = fmaxf(bx, fmaf(tp.x + yb.x, sx, txx));
            by = fmaxf(by, fmaf(tp.y + yb.y, sy, tyy));
        }
        bx = fmaxf(bx, 0.f); by = fmaxf(by, 0.f);
        *(float2*)&out[(long long)row * 512 + d] = make_float2(bx, by);
        ss += bx * bx + by * by;
    }
#pragma unroll
    for (int off = 16; off > 0; off >>= 1) ss += __shfl_down_sync(0xffffffffu, ss, off);
    if (lane == 0) sqout[row] = ss;
}

// ---------------------------------------------------------------------------
extern "C" void kernel_launch(void* const* d_in, const int* in_sizes, int n_in,
                              void* d_out, int out_size) {
    const float* x = (const float*)d_in[0];
    const float *W[5], *gg[5], *bb[5], *mm[5], *vv[5];
    for (int i = 0; i < 5; i++) {
        W[i]  = (const float*)d_in[1 + 5 * i];
        gg[i] = (const float*)d_in[2 + 5 * i];
        bb[i] = (const float*)d_in[3 + 5 * i];
        mm[i] = (const float*)d_in[4 + 5 * i];
        vv[i] = (const float*)d_in[5 + 5 * i];
    }
    float *xcat, *ytb, *sqp, *pdp; int* idxp;
    cudaGetSymbolAddress((void**)&xcat, g_xcat);
    cudaGetSymbolAddress((void**)&ytb, g_ytb);
    cudaGetSymbolAddress((void**)&sqp, g_sq);
    cudaGetSymbolAddress((void**)&idxp, g_idx);
    cudaGetSymbolAddress((void**)&pdp, g_pd);

    static bool tinit = false;
    if (!tinit) {
        cudaFuncSetAttribute(topk_kernel, cudaFuncAttributeMaxDynamicSharedMemorySize,
                             8 * 2048 * 4);
        tinit = true;
    }

    const int Cs[4] = {3, 64, 64, 128};
    const int Ds[4] = {64, 64, 128, 256};

    sqnorm_kernel<<<NROWS / 256, 256>>>(x, 3, 3, sqp);

    const float* in = x;
    int lda = 3;
    int coloff = 0;
    for (int s = 0; s < 4; s++) {
        const int C = Cs[s], D = Ds[s];
        pdgemm_kernel<<<dim3(NPTS / 64, NROWS / 128), 256>>>(in, lda, C, sqp, pdp);
        topk_kernel<<<NROWS / 8, 256, 8 * 2048 * 4>>>(pdp, idxp);
        sgemm_kernel<<<dim3(2 * D / 64, NROWS / 128), 256>>>(in, lda, W[s], C, D, 1,
                                                             ytb, 2 * D,
                                                             nullptr, nullptr, nullptr, nullptr);
        float* outp = xcat + coloff;
        gathermax_kernel<<<NROWS / 8, 256>>>(ytb, idxp, D, gg[s], bb[s], mm[s], vv[s],
                                             outp, sqp);
        in = outp; lda = 512;
        coloff += D;
    }
    sgemm_kernel<<<dim3(512 / 64, NROWS / 128), 256>>>(xcat, 512, W[4], 512, 512, 0,
                                                       (float*)d_out, 512,
                                                       gg[4], bb[4], mm[4], vv[4]);
}

// round 14
// speedup vs baseline: 3.0338x; 1.0280x over previous
#include <cuda_runtime.h>
#include <math_constants.h>

#define BN_EPS 1e-3f
#define NPTS 2048
#define NBATCH 8
#define NROWS (NPTS * NBATCH)
#define KNN 16

typedef unsigned long long u64;

__device__ float g_xcat[NROWS * 512];
__device__ float g_ytb[NROWS * 512];
__device__ float g_sq[NROWS];
__device__ int   g_idx[NROWS * KNN];
__device__ float g_pd[(long long)NROWS * NPTS];   // 134MB distance matrix

// ---------------- f32x2 packed helpers (FFMA2: 2x fp32 throughput) ----------
__device__ __forceinline__ void ffma2(u64& d, u64 a, u64 b) {
    asm("fma.rn.f32x2 %0, %1, %2, %0;" : "+l"(d) : "l"(a), "l"(b));
}
__device__ __forceinline__ float2 unpack2(u64 v) {
    float2 r;
    asm("mov.b64 {%0, %1}, %2;" : "=f"(r.x), "=f"(r.y) : "l"(v));
    return r;
}

// ---------------------------------------------------------------------------
__global__ void sqnorm_kernel(const float* __restrict__ x, int lda, int C,
                              float* __restrict__ sq) {
    int i = blockIdx.x * blockDim.x + threadIdx.x;
    if (i < NROWS) {
        const float* p = x + (long long)i * lda;
        float s = 0.f;
        for (int c = 0; c < C; c++) { float v = p[c]; s = fmaf(v, v, s); }
        sq[i] = s;
    }
}

// ---------------------------------------------------------------------------
// Phase A: pd[i, j] = 2*dot(x_i, x_j) - sq_i - sq_j. Pure GEMM.
// 128x64 tiles, 256 threads (16x16), 8x4 micro-tile in f32x2 (acc = 32 regs).
// launch_bounds(256,2): cap 128 regs -> 2 blocks/SM for latency hiding.
// ---------------------------------------------------------------------------
__global__ void __launch_bounds__(256, 2)
pdgemm_kernel(const float* __restrict__ x, int lda, int K,
              const float* __restrict__ sq,
              float* __restrict__ pd) {
    __shared__ float As[2][16 * 264];
    __shared__ float Bs[2][16 * 68];
    const int mb = blockIdx.y * 128;             // global i tile (within batch)
    const int batch0 = (mb >> 11) << 11;         // batch row base
    const int jb = blockIdx.x * 64;              // local j tile
    const int jrow0 = batch0 + jb;
    const int tid = threadIdx.x;
    const int ty = tid >> 4, tx = tid & 15;
    u64 acc[8][2];
#pragma unroll
    for (int r = 0; r < 8; r++) { acc[r][0] = 0ull; acc[r][1] = 0ull; }
    float ra[8], rb[4];

#pragma unroll
    for (int u = 0; u < 8; u++) {
        int t = tid + u * 256; int m = t >> 4, k = t & 15;
        ra[u] = (k < K) ? x[(long long)(mb + m) * lda + k] : 0.f;
    }
#pragma unroll
    for (int u = 0; u < 4; u++) {
        int t = tid + u * 256; int n = t >> 4, k = t & 15;
        rb[u] = (k < K) ? x[(long long)(jrow0 + n) * lda + k] : 0.f;
    }
#pragma unroll
    for (int u = 0; u < 8; u++) {
        int t = tid + u * 256;
        As[0][(t & 15) * 264 + 2 * (t >> 4)] = ra[u];
        As[0][(t & 15) * 264 + 2 * (t >> 4) + 1] = ra[u];
    }
#pragma unroll
    for (int u = 0; u < 4; u++) {
        int t = tid + u * 256;
        Bs[0][(t & 15) * 68 + (t >> 4)] = rb[u];
    }
    __syncthreads();

    int p = 0;
    for (int kt = 0; kt < K; kt += 16) {
        const bool more = (kt + 16 < K);
        if (more) {
#pragma unroll
            for (int u = 0; u < 8; u++) {
                int t = tid + u * 256; int m = t >> 4, k = kt + 16 + (t & 15);
                ra[u] = (k < K) ? x[(long long)(mb + m) * lda + k] : 0.f;
            }
#pragma unroll
            for (int u = 0; u < 4; u++) {
                int t = tid + u * 256; int n = t >> 4, k = kt + 16 + (t & 15);
                rb[u] = (k < K) ? x[(long long)(jrow0 + n) * lda + k] : 0.f;
            }
        }
        const float* ap = &As[p][ty * 16];
        const float* bp = &Bs[p][tx * 4];
#pragma unroll
        for (int k = 0; k < 16; k++) {
            ulonglong2 a01 = *(const ulonglong2*)(ap + k * 264);
            ulonglong2 a23 = *(const ulonglong2*)(ap + k * 264 + 4);
            ulonglong2 a45 = *(const ulonglong2*)(ap + k * 264 + 8);
            ulonglong2 a67 = *(const ulonglong2*)(ap + k * 264 + 12);
            ulonglong2 bq  = *(const ulonglong2*)(bp + k * 68);
            ffma2(acc[0][0], a01.x, bq.x); ffma2(acc[0][1], a01.x, bq.y);
            ffma2(acc[1][0], a01.y, bq.x); ffma2(acc[1][1], a01.y, bq.y);
            ffma2(acc[2][0], a23.x, bq.x); ffma2(acc[2][1], a23.x, bq.y);
            ffma2(acc[3][0], a23.y, bq.x); ffma2(acc[3][1], a23.y, bq.y);
            ffma2(acc[4][0], a45.x, bq.x); ffma2(acc[4][1], a45.x, bq.y);
            ffma2(acc[5][0], a45.y, bq.x); ffma2(acc[5][1], a45.y, bq.y);
            ffma2(acc[6][0], a67.x, bq.x); ffma2(acc[6][1], a67.x, bq.y);
            ffma2(acc[7][0], a67.y, bq.x); ffma2(acc[7][1], a67.y, bq.y);
        }
        if (more) {
            __syncthreads();
#pragma unroll
            for (int u = 0; u < 8; u++) {
                int t = tid + u * 256;
                As[p ^ 1][(t & 15) * 264 + 2 * (t >> 4)] = ra[u];
                As[p ^ 1][(t & 15) * 264 + 2 * (t >> 4) + 1] = ra[u];
            }
#pragma unroll
            for (int u = 0; u < 4; u++) {
                int t = tid + u * 256;
                Bs[p ^ 1][(t & 15) * 68 + (t >> 4)] = rb[u];
            }
            __syncthreads();
            p ^= 1;
        }
    }

    // epilogue: 2*acc - sqi - sqj -> global pd
    float4 sj = *(const float4*)&sq[jrow0 + tx * 4];
#pragma unroll
    for (int i = 0; i < 8; i++) {
        float sqi = sq[mb + ty * 8 + i];
        float2 lo = unpack2(acc[i][0]);
        float2 hi = unpack2(acc[i][1]);
        float4 o;
        o.x = 2.f * lo.x - sqi - sj.x;
        o.y = 2.f * lo.y - sqi - sj.y;
        o.z = 2.f * hi.x - sqi - sj.z;
        o.w = 2.f * hi.y - sqi - sj.w;
        *(float4*)&pd[(long long)(mb + ty * 8 + i) * NPTS + jb + tx * 4] = o;
    }
}

// ---------------------------------------------------------------------------
// Phase B: exact top-16 per row, warp per row, per-lane TOP-2 tracking so the
// serial rescan only fires when a lane's second is exhausted.
// Ties -> lower index (matches jax.lax.top_k).
// ---------------------------------------------------------------------------
__global__ void topk_kernel(const float* __restrict__ pd, int* __restrict__ outidx) {
    extern __shared__ float rows[];                 // 8 warps x 2048 floats
    const int warp = threadIdx.x >> 5, lane = threadIdx.x & 31;
    const long long row = (long long)blockIdx.x * 8 + warp;
    float* rb = rows + warp * 2048;
    const float4* src = (const float4*)(pd + row * NPTS);
#pragma unroll
    for (int i = 0; i < 16; i++)
        ((float4*)rb)[lane + i * 32] = src[lane + i * 32];
    __syncwarp();

    float bestv = -CUDART_INF_F, secondv = -CUDART_INF_F;
    int besti = 0x7fffffff, seci = -1;
#pragma unroll 8
    for (int s = 0; s < 64; s++) {
        float pv = rb[lane + 32 * s];
        int ix = lane + 32 * s;
        if (pv > bestv) {
            secondv = bestv; seci = besti;
            bestv = pv; besti = ix;
        } else if (pv > secondv) {
            secondv = pv; seci = ix;
        }
    }

    for (int t = 0; t < KNN; t++) {
        float wv = bestv; int wi = besti;
#pragma unroll
        for (int off = 16; off > 0; off >>= 1) {
            float ov = __shfl_xor_sync(0xffffffffu, wv, off);
            int oi = __shfl_xor_sync(0xffffffffu, wi, off);
            if (ov > wv || (ov == wv && oi < wi)) { wv = ov; wi = oi; }
        }
        if (lane == 0) outidx[row * KNN + t] = wi;
        if (besti == wi) {                 // unique winner lane
            rb[wi] = -CUDART_INF_F;
            if (seci >= 0) {               // promote second
                bestv = secondv; besti = seci;
                secondv = -CUDART_INF_F; seci = -1;
            } else {                       // rare: rescan top-2
                bestv = -CUDART_INF_F; secondv = -CUDART_INF_F;
                besti = 0x7fffffff; seci = -1;
#pragma unroll 8
                for (int s = 0; s < 64; s++) {
                    float pv = rb[lane + 32 * s];
                    int ix = lane + 32 * s;
                    if (pv > bestv) {
                        secondv = bestv; seci = besti;
                        bestv = pv; besti = ix;
                    } else if (pv > secondv) {
                        secondv = pv; seci = ix;
                    }
                }
            }
        }
    }
}

// ---------------------------------------------------------------------------
// SGEMM 128x64x16, 256 threads, 8x4 micro-tile in f32x2, double-buffered.
// launch_bounds(256,2): 2 blocks/SM. dual: out = A @ [Wtop|Wbot]. BN+ReLU opt.
// ---------------------------------------------------------------------------
__global__ void __launch_bounds__(256, 2)
sgemm_kernel(const float* __restrict__ A, int lda,
             const float* __restrict__ W, int K, int D, int dual,
             float* __restrict__ Co, int ldc,
             const float* __restrict__ bg, const float* __restrict__ bb,
             const float* __restrict__ bm, const float* __restrict__ bvv) {
    __shared__ float As[2][16 * 264];
    __shared__ float Bs[2][16 * 68];
    const int mb = blockIdx.y * 128, nb = blockIdx.x * 64;
    const int tid = threadIdx.x;
    const int ty = tid >> 4, tx = tid & 15;
    u64 acc[8][2];
#pragma unroll
    for (int r = 0; r < 8; r++) { acc[r][0] = 0ull; acc[r][1] = 0ull; }
    float ra[8], rb[4];

#pragma unroll
    for (int u = 0; u < 8; u++) {
        int t = tid + u * 256; int m = t >> 4, k = t & 15;
        ra[u] = (k < K) ? A[(long long)(mb + m) * lda + k] : 0.f;
    }
#pragma unroll
    for (int u = 0; u < 4; u++) {
        int t = tid + u * 256; int k = t >> 6, n = t & 63;
        int gn = nb + n;
        float val = 0.f;
        if (k < K) {
            if (!dual) val = W[(long long)k * D + gn];
            else if (gn < D) val = W[(long long)k * D + gn];
            else val = W[(long long)(K + k) * D + gn - D];
        }
        rb[u] = val;
    }
#pragma unroll
    for (int u = 0; u < 8; u++) {
        int t = tid + u * 256;
        As[0][(t & 15) * 264 + 2 * (t >> 4)] = ra[u];
        As[0][(t & 15) * 264 + 2 * (t >> 4) + 1] = ra[u];
    }
#pragma unroll
    for (int u = 0; u < 4; u++) {
        int t = tid + u * 256;
        Bs[0][(t >> 6) * 68 + (t & 63)] = rb[u];
    }
    __syncthreads();

    int p = 0;
    for (int kt = 0; kt < K; kt += 16) {
        const bool more = (kt + 16 < K);
        if (more) {
#pragma unroll
            for (int u = 0; u < 8; u++) {
                int t = tid + u * 256; int m = t >> 4, k = kt + 16 + (t & 15);
                ra[u] = (k < K) ? A[(long long)(mb + m) * lda + k] : 0.f;
            }
#pragma unroll
            for (int u = 0; u < 4; u++) {
                int t = tid + u * 256; int k = kt + 16 + (t >> 6), n = t & 63;
                int gn = nb + n;
                float val = 0.f;
                if (k < K) {
                    if (!dual) val = W[(long long)k * D + gn];
                    else if (gn < D) val = W[(long long)k * D + gn];
                    else val = W[(long long)(K + k) * D + gn - D];
                }
                rb[u] = val;
            }
        }
        const float* ap = &As[p][ty * 16];
        const float* bp = &Bs[p][tx * 4];
#pragma unroll
        for (int k = 0; k < 16; k++) {
            ulonglong2 a01 = *(const ulonglong2*)(ap + k * 264);
            ulonglong2 a23 = *(const ulonglong2*)(ap + k * 264 + 4);
            ulonglong2 a45 = *(const ulonglong2*)(ap + k * 264 + 8);
            ulonglong2 a67 = *(const ulonglong2*)(ap + k * 264 + 12);
            ulonglong2 bq  = *(const ulonglong2*)(bp + k * 68);
            ffma2(acc[0][0], a01.x, bq.x); ffma2(acc[0][1], a01.x, bq.y);
            ffma2(acc[1][0], a01.y, bq.x); ffma2(acc[1][1], a01.y, bq.y);
            ffma2(acc[2][0], a23.x, bq.x); ffma2(acc[2][1], a23.x, bq.y);
            ffma2(acc[3][0], a23.y, bq.x); ffma2(acc[3][1], a23.y, bq.y);
            ffma2(acc[4][0], a45.x, bq.x); ffma2(acc[4][1], a45.x, bq.y);
            ffma2(acc[5][0], a45.y, bq.x); ffma2(acc[5][1], a45.y, bq.y);
            ffma2(acc[6][0], a67.x, bq.x); ffma2(acc[6][1], a67.x, bq.y);
            ffma2(acc[7][0], a67.y, bq.x); ffma2(acc[7][1], a67.y, bq.y);
        }
        if (more) {
            __syncthreads();
#pragma unroll
            for (int u = 0; u < 8; u++) {
                int t = tid + u * 256;
                As[p ^ 1][(t & 15) * 264 + 2 * (t >> 4)] = ra[u];
                As[p ^ 1][(t & 15) * 264 + 2 * (t >> 4) + 1] = ra[u];
            }
#pragma unroll
            for (int u = 0; u < 4; u++) {
                int t = tid + u * 256;
                Bs[p ^ 1][(t >> 6) * 68 + (t & 63)] = rb[u];
            }
            __syncthreads();
            p ^= 1;
        }
    }

    float s4[4], t4[4];
    if (bg) {
#pragma unroll
        for (int j = 0; j < 4; j++) {
            int n = nb + tx * 4 + j;
            s4[j] = bg[n] * rsqrtf(bvv[n] + BN_EPS);
            t4[j] = bb[n] - bm[n] * s4[j];
        }
    }
#pragma unroll
    for (int i = 0; i < 8; i++) {
        float2 lo = unpack2(acc[i][0]);
        float2 hi = unpack2(acc[i][1]);
        float o[4] = {lo.x, lo.y, hi.x, hi.y};
        if (bg) {
#pragma unroll
            for (int j = 0; j < 4; j++)
                o[j] = fmaxf(fmaf(o[j], s4[j], t4[j]), 0.f);
        }
        *(float4*)&Co[(long long)(mb + ty * 8 + i) * ldc + nb + tx * 4] =
            make_float4(o[0], o[1], o[2], o[3]);
    }
}

// ---------------------------------------------------------------------------
// gather + BN + ReLU + max over k=16; fused next-stage sqnorm. Warp per row.
// ---------------------------------------------------------------------------
__global__ void gathermax_kernel(const float* __restrict__ ytb, const int* __restrict__ idx,
                                 int D,
                                 const float* __restrict__ g, const float* __restrict__ b,
                                 const float* __restrict__ m, const float* __restrict__ vv,
                                 float* __restrict__ out, float* __restrict__ sqout) {
    const int warp = (blockIdx.x * blockDim.x + threadIdx.x) >> 5;
    const int lane = threadIdx.x & 31;
    if (warp >= NROWS) return;
    const int row = warp;
    const int base = row & ~(NPTS - 1);
    const int myid = idx[(long long)row * KNN + (lane & 15)];
    const float* top = ytb + (long long)row * 2 * D;
    float ss = 0.f;
    for (int c0 = 0; c0 < D; c0 += 64) {
        const int d = c0 + lane * 2;
        float2 g2 = *(const float2*)&g[d];
        float2 v2 = *(const float2*)&vv[d];
        float2 b2 = *(const float2*)&b[d];
        float2 m2 = *(const float2*)&m[d];
        float sx = g2.x * rsqrtf(v2.x + BN_EPS), txx = b2.x - m2.x * sx;
        float sy = g2.y * rsqrtf(v2.y + BN_EPS), tyy = b2.y - m2.y * sy;
        float2 tp = *(const float2*)&top[d];
        float bx = -CUDART_INF_F, by = -CUDART_INF_F;
#pragma unroll
        for (int k = 0; k < KNN; k++) {
            int sk = __shfl_sync(0xffffffffu, myid, k, 16);
            float2 yb = *(const float2*)&ytb[(long long)(base + sk) * 2 * D + D + d];
            bx = fmaxf(bx, fmaf(tp.x + yb.x, sx, txx));
            by = fmaxf(by, fmaf(tp.y + yb.y, sy, tyy));
        }
        bx = fmaxf(bx, 0.f); by = fmaxf(by, 0.f);
        *(float2*)&out[(long long)row * 512 + d] = make_float2(bx, by);
        ss += bx * bx + by * by;
    }
#pragma unroll
    for (int off = 16; off > 0; off >>= 1) ss += __shfl_down_sync(0xffffffffu, ss, off);
    if (lane == 0) sqout[row] = ss;
}

// ---------------------------------------------------------------------------
extern "C" void kernel_launch(void* const* d_in, const int* in_sizes, int n_in,
                              void* d_out, int out_size) {
    const float* x = (const float*)d_in[0];
    const float *W[5], *gg[5], *bb[5], *mm[5], *vv[5];
    for (int i = 0; i < 5; i++) {
        W[i]  = (const float*)d_in[1 + 5 * i];
        gg[i] = (const float*)d_in[2 + 5 * i];
        bb[i] = (const float*)d_in[3 + 5 * i];
        mm[i] = (const float*)d_in[4 + 5 * i];
        vv[i] = (const float*)d_in[5 + 5 * i];
    }
    float *xcat, *ytb, *sqp, *pdp; int* idxp;
    cudaGetSymbolAddress((void**)&xcat, g_xcat);
    cudaGetSymbolAddress((void**)&ytb, g_ytb);
    cudaGetSymbolAddress((void**)&sqp, g_sq);
    cudaGetSymbolAddress((void**)&idxp, g_idx);
    cudaGetSymbolAddress((void**)&pdp, g_pd);

    static bool tinit = false;
    if (!tinit) {
        cudaFuncSetAttribute(topk_kernel, cudaFuncAttributeMaxDynamicSharedMemorySize,
                             8 * 2048 * 4);
        tinit = true;
    }

    const int Cs[4] = {3, 64, 64, 128};
    const int Ds[4] = {64, 64, 128, 256};

    sqnorm_kernel<<<NROWS / 256, 256>>>(x, 3, 3, sqp);

    const float* in = x;
    int lda = 3;
    int coloff = 0;
    for (int s = 0; s < 4; s++) {
        const int C = Cs[s], D = Ds[s];
        pdgemm_kernel<<<dim3(NPTS / 64, NROWS / 128), 256>>>(in, lda, C, sqp, pdp);
        topk_kernel<<<NROWS / 8, 256, 8 * 2048 * 4>>>(pdp, idxp);
        sgemm_kernel<<<dim3(2 * D / 64, NROWS / 128), 256>>>(in, lda, W[s], C, D, 1,
                                                             ytb, 2 * D,
                                                             nullptr, nullptr, nullptr, nullptr);
        float* outp = xcat + coloff;
        gathermax_kernel<<<NROWS / 8, 256>>>(ytb, idxp, D, gg[s], bb[s], mm[s], vv[s],
                                             outp, sqp);
        in = outp; lda = 512;
        coloff += D;
    }
    sgemm_kernel<<<dim3(512 / 64, NROWS / 128), 256>>>(xcat, 512, W[4], 512, 512, 0,
                                                       (float*)d_out, 512,
                                                       gg[4], bb[4], mm[4], vv[4]);
}

// round 15
// speedup vs baseline: 3.5879x; 1.1826x over previous
#include <cuda_runtime.h>
#include <math_constants.h>

#define BN_EPS 1e-3f
#define NPTS 2048
#define NBATCH 8
#define NROWS (NPTS * NBATCH)
#define KNN 16

typedef unsigned long long u64;

__device__ float g_xcat[NROWS * 512];
__device__ float g_ytb[NROWS * 512];
__device__ float g_sq[NROWS];
__device__ int   g_idx[NROWS * KNN];
__device__ float g_pd[(long long)NROWS * NPTS];   // 134MB distance matrix

// ---------------- f32x2 packed helpers (FFMA2: 2x fp32 throughput) ----------
__device__ __forceinline__ void ffma2(u64& d, u64 a, u64 b) {
    asm("fma.rn.f32x2 %0, %1, %2, %0;" : "+l"(d) : "l"(a), "l"(b));
}
__device__ __forceinline__ float2 unpack2(u64 v) {
    float2 r;
    asm("mov.b64 {%0, %1}, %2;" : "=f"(r.x), "=f"(r.y) : "l"(v));
    return r;
}

// ---------------------------------------------------------------------------
__global__ void sqnorm_kernel(const float* __restrict__ x, int lda, int C,
                              float* __restrict__ sq) {
    int i = blockIdx.x * blockDim.x + threadIdx.x;
    if (i < NROWS) {
        const float* p = x + (long long)i * lda;
        float s = 0.f;
        for (int c = 0; c < C; c++) { float v = p[c]; s = fmaf(v, v, s); }
        sq[i] = s;
    }
}

// ---------------------------------------------------------------------------
// Phase A: pd[i, j] = 2*dot - sqi - sqj, SYMMETRY-EXPLOITING.
// Per batch: i-tiles I (128 rows), j-tiles J (64 cols). Compute only J >= 2I;
// tiles with J >= 2I+2 also emit the mirrored tile (staged via smem for
// coalescing). Coverage is exact & writer-unique -> deterministic.
// ---------------------------------------------------------------------------
__global__ void __launch_bounds__(256, 2)
pdgemm_kernel(const float* __restrict__ x, int lda, int K,
              const float* __restrict__ sq,
              float* __restrict__ pd) {
    __shared__ float smflat[10624];      // As(8448) + Bs(2176); reused as tbuf
    float* As = smflat;                  // [2][16*264]
    float* Bs = smflat + 8448;           // [2][16*68]

    const int Ig = blockIdx.y;           // global 128-row i tile
    const int Il = Ig & 15;              // i tile within batch
    const int J = blockIdx.x;            // 64-col j tile within batch
    if (J < 2 * Il) return;              // mirror covered elsewhere
    const bool dotrans = (J >= 2 * Il + 2);

    const int mb = Ig * 128;
    const int batch0 = (mb >> 11) << 11;
    const int jb = J * 64;
    const int jrow0 = batch0 + jb;
    const int tid = threadIdx.x;
    const int ty = tid >> 4, tx = tid & 15;
    u64 acc[8][2];
#pragma unroll
    for (int r = 0; r < 8; r++) { acc[r][0] = 0ull; acc[r][1] = 0ull; }
    float ra[8], rb[4];

#pragma unroll
    for (int u = 0; u < 8; u++) {
        int t = tid + u * 256; int m = t >> 4, k = t & 15;
        ra[u] = (k < K) ? x[(long long)(mb + m) * lda + k] : 0.f;
    }
#pragma unroll
    for (int u = 0; u < 4; u++) {
        int t = tid + u * 256; int n = t >> 4, k = t & 15;
        rb[u] = (k < K) ? x[(long long)(jrow0 + n) * lda + k] : 0.f;
    }
#pragma unroll
    for (int u = 0; u < 8; u++) {
        int t = tid + u * 256;
        As[(t & 15) * 264 + 2 * (t >> 4)] = ra[u];
        As[(t & 15) * 264 + 2 * (t >> 4) + 1] = ra[u];
    }
#pragma unroll
    for (int u = 0; u < 4; u++) {
        int t = tid + u * 256;
        Bs[(t & 15) * 68 + (t >> 4)] = rb[u];
    }
    __syncthreads();

    int p = 0;
    for (int kt = 0; kt < K; kt += 16) {
        const bool more = (kt + 16 < K);
        if (more) {
#pragma unroll
            for (int u = 0; u < 8; u++) {
                int t = tid + u * 256; int m = t >> 4, k = kt + 16 + (t & 15);
                ra[u] = (k < K) ? x[(long long)(mb + m) * lda + k] : 0.f;
            }
#pragma unroll
            for (int u = 0; u < 4; u++) {
                int t = tid + u * 256; int n = t >> 4, k = kt + 16 + (t & 15);
                rb[u] = (k < K) ? x[(long long)(jrow0 + n) * lda + k] : 0.f;
            }
        }
        const float* ap = As + p * 16 * 264 + ty * 16;
        const float* bp = Bs + p * 16 * 68 + tx * 4;
#pragma unroll
        for (int k = 0; k < 16; k++) {
            ulonglong2 a01 = *(const ulonglong2*)(ap + k * 264);
            ulonglong2 a23 = *(const ulonglong2*)(ap + k * 264 + 4);
            ulonglong2 a45 = *(const ulonglong2*)(ap + k * 264 + 8);
            ulonglong2 a67 = *(const ulonglong2*)(ap + k * 264 + 12);
            ulonglong2 bq  = *(const ulonglong2*)(bp + k * 68);
            ffma2(acc[0][0], a01.x, bq.x); ffma2(acc[0][1], a01.x, bq.y);
            ffma2(acc[1][0], a01.y, bq.x); ffma2(acc[1][1], a01.y, bq.y);
            ffma2(acc[2][0], a23.x, bq.x); ffma2(acc[2][1], a23.x, bq.y);
            ffma2(acc[3][0], a23.y, bq.x); ffma2(acc[3][1], a23.y, bq.y);
            ffma2(acc[4][0], a45.x, bq.x); ffma2(acc[4][1], a45.x, bq.y);
            ffma2(acc[5][0], a45.y, bq.x); ffma2(acc[5][1], a45.y, bq.y);
            ffma2(acc[6][0], a67.x, bq.x); ffma2(acc[6][1], a67.x, bq.y);
            ffma2(acc[7][0], a67.y, bq.x); ffma2(acc[7][1], a67.y, bq.y);
        }
        if (more) {
            __syncthreads();
#pragma unroll
            for (int u = 0; u < 8; u++) {
                int t = tid + u * 256;
                As[(p ^ 1) * 16 * 264 + (t & 15) * 264 + 2 * (t >> 4)] = ra[u];
                As[(p ^ 1) * 16 * 264 + (t & 15) * 264 + 2 * (t >> 4) + 1] = ra[u];
            }
#pragma unroll
            for (int u = 0; u < 4; u++) {
                int t = tid + u * 256;
                Bs[(p ^ 1) * 16 * 68 + (t & 15) * 68 + (t >> 4)] = rb[u];
            }
            __syncthreads();
            p ^= 1;
        }
    }

    // epilogue: direct writes (+ staged transpose when dotrans)
    if (dotrans) __syncthreads();   // GEMM smem dead; reuse as transpose buf
    float* tb = smflat;             // 64 x 129 floats = 8256 <= 10624
    float4 sj = *(const float4*)&sq[jrow0 + tx * 4];
#pragma unroll
    for (int i = 0; i < 8; i++) {
        float sqi = sq[mb + ty * 8 + i];
        float2 lo = unpack2(acc[i][0]);
        float2 hi = unpack2(acc[i][1]);
        float4 o;
        o.x = 2.f * lo.x - sqi - sj.x;
        o.y = 2.f * lo.y - sqi - sj.y;
        o.z = 2.f * hi.x - sqi - sj.z;
        o.w = 2.f * hi.y - sqi - sj.w;
        *(float4*)&pd[(long long)(mb + ty * 8 + i) * NPTS + jb + tx * 4] = o;
        if (dotrans) {
            int ii = ty * 8 + i;
            tb[(tx * 4 + 0) * 129 + ii] = o.x;
            tb[(tx * 4 + 1) * 129 + ii] = o.y;
            tb[(tx * 4 + 2) * 129 + ii] = o.z;
            tb[(tx * 4 + 3) * 129 + ii] = o.w;
        }
    }
    if (dotrans) {
        __syncthreads();
        const int mloc = mb - batch0;   // batch-local i base (pd column)
#pragma unroll
        for (int u = 0; u < 8; u++) {
            int idx = tid + u * 256;    // 0..2047
            int row = idx >> 5;         // j within tile
            int q = idx & 31;           // i quad
            const float* s = tb + row * 129 + 4 * q;
            float4 v = make_float4(s[0], s[1], s[2], s[3]);
            *(float4*)&pd[(long long)(jrow0 + row) * NPTS + mloc + 4 * q] = v;
        }
    }
}

// ---------------------------------------------------------------------------
// Phase B: exact top-16 per row, warp per row, per-lane TOP-2 tracking.
// Ties -> lower index (matches jax.lax.top_k).
// ---------------------------------------------------------------------------
__global__ void topk_kernel(const float* __restrict__ pd, int* __restrict__ outidx) {
    extern __shared__ float rows[];                 // 8 warps x 2048 floats
    const int warp = threadIdx.x >> 5, lane = threadIdx.x & 31;
    const long long row = (long long)blockIdx.x * 8 + warp;
    float* rb = rows + warp * 2048;
    const float4* src = (const float4*)(pd + row * NPTS);
#pragma unroll
    for (int i = 0; i < 16; i++)
        ((float4*)rb)[lane + i * 32] = src[lane + i * 32];
    __syncwarp();

    float bestv = -CUDART_INF_F, secondv = -CUDART_INF_F;
    int besti = 0x7fffffff, seci = -1;
#pragma unroll 8
    for (int s = 0; s < 64; s++) {
        float pv = rb[lane + 32 * s];
        int ix = lane + 32 * s;
        if (pv > bestv) {
            secondv = bestv; seci = besti;
            bestv = pv; besti = ix;
        } else if (pv > secondv) {
            secondv = pv; seci = ix;
        }
    }

    for (int t = 0; t < KNN; t++) {
        float wv = bestv; int wi = besti;
#pragma unroll
        for (int off = 16; off > 0; off >>= 1) {
            float ov = __shfl_xor_sync(0xffffffffu, wv, off);
            int oi = __shfl_xor_sync(0xffffffffu, wi, off);
            if (ov > wv || (ov == wv && oi < wi)) { wv = ov; wi = oi; }
        }
        if (lane == 0) outidx[row * KNN + t] = wi;
        if (besti == wi) {                 // unique winner lane
            rb[wi] = -CUDART_INF_F;
            if (seci >= 0) {               // promote second
                bestv = secondv; besti = seci;
                secondv = -CUDART_INF_F; seci = -1;
            } else {                       // rare: rescan top-2
                bestv = -CUDART_INF_F; secondv = -CUDART_INF_F;
                besti = 0x7fffffff; seci = -1;
#pragma unroll 8
                for (int s = 0; s < 64; s++) {
                    float pv = rb[lane + 32 * s];
                    int ix = lane + 32 * s;
                    if (pv > bestv) {
                        secondv = bestv; seci = besti;
                        bestv = pv; besti = ix;
                    } else if (pv > secondv) {
                        secondv = pv; seci = ix;
                    }
                }
            }
        }
    }
}

// ---------------------------------------------------------------------------
// SGEMM 128x64x16, 256 threads, 8x4 micro-tile in f32x2, double-buffered.
// launch_bounds(256,2). dual: out = A @ [Wtop|Wbot]. Optional BN+ReLU.
// ---------------------------------------------------------------------------
__global__ void __launch_bounds__(256, 2)
sgemm_kernel(const float* __restrict__ A, int lda,
             const float* __restrict__ W, int K, int D, int dual,
             float* __restrict__ Co, int ldc,
             const float* __restrict__ bg, const float* __restrict__ bb,
             const float* __restrict__ bm, const float* __restrict__ bvv) {
    __shared__ float As[2][16 * 264];
    __shared__ float Bs[2][16 * 68];
    const int mb = blockIdx.y * 128, nb = blockIdx.x * 64;
    const int tid = threadIdx.x;
    const int ty = tid >> 4, tx = tid & 15;
    u64 acc[8][2];
#pragma unroll
    for (int r = 0; r < 8; r++) { acc[r][0] = 0ull; acc[r][1] = 0ull; }
    float ra[8], rb[4];

#pragma unroll
    for (int u = 0; u < 8; u++) {
        int t = tid + u * 256; int m = t >> 4, k = t & 15;
        ra[u] = (k < K) ? A[(long long)(mb + m) * lda + k] : 0.f;
    }
#pragma unroll
    for (int u = 0; u < 4; u++) {
        int t = tid + u * 256; int k = t >> 6, n = t & 63;
        int gn = nb + n;
        float val = 0.f;
        if (k < K) {
            if (!dual) val = W[(long long)k * D + gn];
            else if (gn < D) val = W[(long long)k * D + gn];
            else val = W[(long long)(K + k) * D + gn - D];
        }
        rb[u] = val;
    }
#pragma unroll
    for (int u = 0; u < 8; u++) {
        int t = tid + u * 256;
        As[0][(t & 15) * 264 + 2 * (t >> 4)] = ra[u];
        As[0][(t & 15) * 264 + 2 * (t >> 4) + 1] = ra[u];
    }
#pragma unroll
    for (int u = 0; u < 4; u++) {
        int t = tid + u * 256;
        Bs[0][(t >> 6) * 68 + (t & 63)] = rb[u];
    }
    __syncthreads();

    int p = 0;
    for (int kt = 0; kt < K; kt += 16) {
        const bool more = (kt + 16 < K);
        if (more) {
#pragma unroll
            for (int u = 0; u < 8; u++) {
                int t = tid + u * 256; int m = t >> 4, k = kt + 16 + (t & 15);
                ra[u] = (k < K) ? A[(long long)(mb + m) * lda + k] : 0.f;
            }
#pragma unroll
            for (int u = 0; u < 4; u++) {
                int t = tid + u * 256; int k = kt + 16 + (t >> 6), n = t & 63;
                int gn = nb + n;
                float val = 0.f;
                if (k < K) {
                    if (!dual) val = W[(long long)k * D + gn];
                    else if (gn < D) val = W[(long long)k * D + gn];
                    else val = W[(long long)(K + k) * D + gn - D];
                }
                rb[u] = val;
            }
        }
        const float* ap = &As[p][ty * 16];
        const float* bp = &Bs[p][tx * 4];
#pragma unroll
        for (int k = 0; k < 16; k++) {
            ulonglong2 a01 = *(const ulonglong2*)(ap + k * 264);
            ulonglong2 a23 = *(const ulonglong2*)(ap + k * 264 + 4);
            ulonglong2 a45 = *(const ulonglong2*)(ap + k * 264 + 8);
            ulonglong2 a67 = *(const ulonglong2*)(ap + k * 264 + 12);
            ulonglong2 bq  = *(const ulonglong2*)(bp + k * 68);
            ffma2(acc[0][0], a01.x, bq.x); ffma2(acc[0][1], a01.x, bq.y);
            ffma2(acc[1][0], a01.y, bq.x); ffma2(acc[1][1], a01.y, bq.y);
            ffma2(acc[2][0], a23.x, bq.x); ffma2(acc[2][1], a23.x, bq.y);
            ffma2(acc[3][0], a23.y, bq.x); ffma2(acc[3][1], a23.y, bq.y);
            ffma2(acc[4][0], a45.x, bq.x); ffma2(acc[4][1], a45.x, bq.y);
            ffma2(acc[5][0], a45.y, bq.x); ffma2(acc[5][1], a45.y, bq.y);
            ffma2(acc[6][0], a67.x, bq.x); ffma2(acc[6][1], a67.x, bq.y);
            ffma2(acc[7][0], a67.y, bq.x); ffma2(acc[7][1], a67.y, bq.y);
        }
        if (more) {
            __syncthreads();
#pragma unroll
            for (int u = 0; u < 8; u++) {
                int t = tid + u * 256;
                As[p ^ 1][(t & 15) * 264 + 2 * (t >> 4)] = ra[u];
                As[p ^ 1][(t & 15) * 264 + 2 * (t >> 4) + 1] = ra[u];
            }
#pragma unroll
            for (int u = 0; u < 4; u++) {
                int t = tid + u * 256;
                Bs[p ^ 1][(t >> 6) * 68 + (t & 63)] = rb[u];
            }
            __syncthreads();
            p ^= 1;
        }
    }

    float s4[4], t4[4];
    if (bg) {
#pragma unroll
        for (int j = 0; j < 4; j++) {
            int n = nb + tx * 4 + j;
            s4[j] = bg[n] * rsqrtf(bvv[n] + BN_EPS);
            t4[j] = bb[n] - bm[n] * s4[j];
        }
    }
#pragma unroll
    for (int i = 0; i < 8; i++) {
        float2 lo = unpack2(acc[i][0]);
        float2 hi = unpack2(acc[i][1]);
        float o[4] = {lo.x, lo.y, hi.x, hi.y};
        if (bg) {
#pragma unroll
            for (int j = 0; j < 4; j++)
                o[j] = fmaxf(fmaf(o[j], s4[j], t4[j]), 0.f);
        }
        *(float4*)&Co[(long long)(mb + ty * 8 + i) * ldc + nb + tx * 4] =
            make_float4(o[0], o[1], o[2], o[3]);
    }
}

// ---------------------------------------------------------------------------
// gather + BN + ReLU + max over k=16; fused next-stage sqnorm. Warp per row.
// ---------------------------------------------------------------------------
__global__ void gathermax_kernel(const float* __restrict__ ytb, const int* __restrict__ idx,
                                 int D,
                                 const float* __restrict__ g, const float* __restrict__ b,
                                 const float* __restrict__ m, const float* __restrict__ vv,
                                 float* __restrict__ out, float* __restrict__ sqout) {
    const int warp = (blockIdx.x * blockDim.x + threadIdx.x) >> 5;
    const int lane = threadIdx.x & 31;
    if (warp >= NROWS) return;
    const int row = warp;
    const int base = row & ~(NPTS - 1);
    const int myid = idx[(long long)row * KNN + (lane & 15)];
    const float* top = ytb + (long long)row * 2 * D;
    float ss = 0.f;
    for (int c0 = 0; c0 < D; c0 += 64) {
        const int d = c0 + lane * 2;
        float2 g2 = *(const float2*)&g[d];
        float2 v2 = *(const float2*)&vv[d];
        float2 b2 = *(const float2*)&b[d];
        float2 m2 = *(const float2*)&m[d];
        float sx = g2.x * rsqrtf(v2.x + BN_EPS), txx = b2.x - m2.x * sx;
        float sy = g2.y * rsqrtf(v2.y + BN_EPS), tyy = b2.y - m2.y * sy;
        float2 tp = *(const float2*)&top[d];
        float bx = -CUDART_INF_F, by = -CUDART_INF_F;
#pragma unroll
        for (int k = 0; k < KNN; k++) {
            int sk = __shfl_sync(0xffffffffu, myid, k, 16);
            float2 yb = *(const float2*)&ytb[(long long)(base + sk) * 2 * D + D + d];
            bx = fmaxf(bx, fmaf(tp.x + yb.x, sx, txx));
            by = fmaxf(by, fmaf(tp.y + yb.y, sy, tyy));
        }
        bx = fmaxf(bx, 0.f); by = fmaxf(by, 0.f);
        *(float2*)&out[(long long)row * 512 + d] = make_float2(bx, by);
        ss += bx * bx + by * by;
    }
#pragma unroll
    for (int off = 16; off > 0; off >>= 1) ss += __shfl_down_sync(0xffffffffu, ss, off);
    if (lane == 0) sqout[row] = ss;
}

// ---------------------------------------------------------------------------
extern "C" void kernel_launch(void* const* d_in, const int* in_sizes, int n_in,
                              void* d_out, int out_size) {
    const float* x = (const float*)d_in[0];
    const float *W[5], *gg[5], *bb[5], *mm[5], *vv[5];
    for (int i = 0; i < 5; i++) {
        W[i]  = (const float*)d_in[1 + 5 * i];
        gg[i] = (const float*)d_in[2 + 5 * i];
        bb[i] = (const float*)d_in[3 + 5 * i];
        mm[i] = (const float*)d_in[4 + 5 * i];
        vv[i] = (const float*)d_in[5 + 5 * i];
    }
    float *xcat, *ytb, *sqp, *pdp; int* idxp;
    cudaGetSymbolAddress((void**)&xcat, g_xcat);
    cudaGetSymbolAddress((void**)&ytb, g_ytb);
    cudaGetSymbolAddress((void**)&sqp, g_sq);
    cudaGetSymbolAddress((void**)&idxp, g_idx);
    cudaGetSymbolAddress((void**)&pdp, g_pd);

    static bool tinit = false;
    if (!tinit) {
        cudaFuncSetAttribute(topk_kernel, cudaFuncAttributeMaxDynamicSharedMemorySize,
                             8 * 2048 * 4);
        tinit = true;
    }

    const int Cs[4] = {3, 64, 64, 128};
    const int Ds[4] = {64, 64, 128, 256};

    sqnorm_kernel<<<NROWS / 256, 256>>>(x, 3, 3, sqp);

    const float* in = x;
    int lda = 3;
    int coloff = 0;
    for (int s = 0; s < 4; s++) {
        const int C = Cs[s], D = Ds[s];
        pdgemm_kernel<<<dim3(NPTS / 64, NROWS / 128), 256>>>(in, lda, C, sqp, pdp);
        topk_kernel<<<NROWS / 8, 256, 8 * 2048 * 4>>>(pdp, idxp);
        sgemm_kernel<<<dim3(2 * D / 64, NROWS / 128), 256>>>(in, lda, W[s], C, D, 1,
                                                             ytb, 2 * D,
                                                             nullptr, nullptr, nullptr, nullptr);
        float* outp = xcat + coloff;
        gathermax_kernel<<<NROWS / 8, 256>>>(ytb, idxp, D, gg[s], bb[s], mm[s], vv[s],
                                             outp, sqp);
        in = outp; lda = 512;
        coloff += D;
    }
    sgemm_kernel<<<dim3(512 / 64, NROWS / 128), 256>>>(xcat, 512, W[4], 512, 512, 0,
                                                       (float*)d_out, 512,
                                                       gg[4], bb[4], mm[4], vv[4]);
}

// round 17
// speedup vs baseline: 3.6419x; 1.0151x over previous
#include <cuda_runtime.h>
#include <math_constants.h>

#define BN_EPS 1e-3f
#define NPTS 2048
#define NBATCH 8
#define NROWS (NPTS * NBATCH)
#define KNN 16

typedef unsigned long long u64;

__device__ float g_xcat[NROWS * 512];
__device__ float g_ytb[NROWS * 512];
__device__ float g_sq[NROWS];
__device__ int   g_idx[NROWS * KNN];
__device__ float g_pd[(long long)NROWS * NPTS];   // 134MB distance matrix

// ---------------- f32x2 packed helpers (FFMA2: 2x fp32 throughput) ----------
__device__ __forceinline__ void ffma2(u64& d, u64 a, u64 b) {
    asm("fma.rn.f32x2 %0, %1, %2, %0;" : "+l"(d) : "l"(a), "l"(b));
}
__device__ __forceinline__ float2 unpack2(u64 v) {
    float2 r;
    asm("mov.b64 {%0, %1}, %2;" : "=f"(r.x), "=f"(r.y) : "l"(v));
    return r;
}

// ---------------------------------------------------------------------------
__global__ void sqnorm_kernel(const float* __restrict__ x, int lda, int C,
                              float* __restrict__ sq) {
    int i = blockIdx.x * blockDim.x + threadIdx.x;
    if (i < NROWS) {
        const float* p = x + (long long)i * lda;
        float s = 0.f;
        for (int c = 0; c < C; c++) { float v = p[c]; s = fmaf(v, v, s); }
        sq[i] = s;
    }
}

// ---------------------------------------------------------------------------
// Phase A: pd[i, j] = 2*dot - sqi - sqj, SYMMETRY-EXPLOITING (R15-proven).
// ---------------------------------------------------------------------------
__global__ void __launch_bounds__(256, 2)
pdgemm_kernel(const float* __restrict__ x, int lda, int K,
              const float* __restrict__ sq,
              float* __restrict__ pd) {
    __shared__ float smflat[10624];      // As(8448) + Bs(2176); reused as tbuf
    float* As = smflat;
    float* Bs = smflat + 8448;

    const int Ig = blockIdx.y;
    const int Il = Ig & 15;
    const int J = blockIdx.x;
    if (J < 2 * Il) return;
    const bool dotrans = (J >= 2 * Il + 2);

    const int mb = Ig * 128;
    const int batch0 = (mb >> 11) << 11;
    const int jb = J * 64;
    const int jrow0 = batch0 + jb;
    const int tid = threadIdx.x;
    const int ty = tid >> 4, tx = tid & 15;
    u64 acc[8][2];
#pragma unroll
    for (int r = 0; r < 8; r++) { acc[r][0] = 0ull; acc[r][1] = 0ull; }
    float ra[8], rb[4];

#pragma unroll
    for (int u = 0; u < 8; u++) {
        int t = tid + u * 256; int m = t >> 4, k = t & 15;
        ra[u] = (k < K) ? x[(long long)(mb + m) * lda + k] : 0.f;
    }
#pragma unroll
    for (int u = 0; u < 4; u++) {
        int t = tid + u * 256; int n = t >> 4, k = t & 15;
        rb[u] = (k < K) ? x[(long long)(jrow0 + n) * lda + k] : 0.f;
    }
#pragma unroll
    for (int u = 0; u < 8; u++) {
        int t = tid + u * 256;
        As[(t & 15) * 264 + 2 * (t >> 4)] = ra[u];
        As[(t & 15) * 264 + 2 * (t >> 4) + 1] = ra[u];
    }
#pragma unroll
    for (int u = 0; u < 4; u++) {
        int t = tid + u * 256;
        Bs[(t & 15) * 68 + (t >> 4)] = rb[u];
    }
    __syncthreads();

    int p = 0;
    for (int kt = 0; kt < K; kt += 16) {
        const bool more = (kt + 16 < K);
        if (more) {
#pragma unroll
            for (int u = 0; u < 8; u++) {
                int t = tid + u * 256; int m = t >> 4, k = kt + 16 + (t & 15);
                ra[u] = (k < K) ? x[(long long)(mb + m) * lda + k] : 0.f;
            }
#pragma unroll
            for (int u = 0; u < 4; u++) {
                int t = tid + u * 256; int n = t >> 4, k = kt + 16 + (t & 15);
                rb[u] = (k < K) ? x[(long long)(jrow0 + n) * lda + k] : 0.f;
            }
        }
        const float* ap = As + p * 16 * 264 + ty * 16;
        const float* bp = Bs + p * 16 * 68 + tx * 4;
#pragma unroll
        for (int k = 0; k < 16; k++) {
            ulonglong2 a01 = *(const ulonglong2*)(ap + k * 264);
            ulonglong2 a23 = *(const ulonglong2*)(ap + k * 264 + 4);
            ulonglong2 a45 = *(const ulonglong2*)(ap + k * 264 + 8);
            ulonglong2 a67 = *(const ulonglong2*)(ap + k * 264 + 12);
            ulonglong2 bq  = *(const ulonglong2*)(bp + k * 68);
            ffma2(acc[0][0], a01.x, bq.x); ffma2(acc[0][1], a01.x, bq.y);
            ffma2(acc[1][0], a01.y, bq.x); ffma2(acc[1][1], a01.y, bq.y);
            ffma2(acc[2][0], a23.x, bq.x); ffma2(acc[2][1], a23.x, bq.y);
            ffma2(acc[3][0], a23.y, bq.x); ffma2(acc[3][1], a23.y, bq.y);
            ffma2(acc[4][0], a45.x, bq.x); ffma2(acc[4][1], a45.x, bq.y);
            ffma2(acc[5][0], a45.y, bq.x); ffma2(acc[5][1], a45.y, bq.y);
            ffma2(acc[6][0], a67.x, bq.x); ffma2(acc[6][1], a67.x, bq.y);
            ffma2(acc[7][0], a67.y, bq.x); ffma2(acc[7][1], a67.y, bq.y);
        }
        if (more) {
            __syncthreads();
#pragma unroll
            for (int u = 0; u < 8; u++) {
                int t = tid + u * 256;
                As[(p ^ 1) * 16 * 264 + (t & 15) * 264 + 2 * (t >> 4)] = ra[u];
                As[(p ^ 1) * 16 * 264 + (t & 15) * 264 + 2 * (t >> 4) + 1] = ra[u];
            }
#pragma unroll
            for (int u = 0; u < 4; u++) {
                int t = tid + u * 256;
                Bs[(p ^ 1) * 16 * 68 + (t & 15) * 68 + (t >> 4)] = rb[u];
            }
            __syncthreads();
            p ^= 1;
        }
    }

    if (dotrans) __syncthreads();
    float* tb = smflat;             // 64 x 129 floats
    float4 sj = *(const float4*)&sq[jrow0 + tx * 4];
#pragma unroll
    for (int i = 0; i < 8; i++) {
        float sqi = sq[mb + ty * 8 + i];
        float2 lo = unpack2(acc[i][0]);
        float2 hi = unpack2(acc[i][1]);
        float4 o;
        o.x = 2.f * lo.x - sqi - sj.x;
        o.y = 2.f * lo.y - sqi - sj.y;
        o.z = 2.f * hi.x - sqi - sj.z;
        o.w = 2.f * hi.y - sqi - sj.w;
        *(float4*)&pd[(long long)(mb + ty * 8 + i) * NPTS + jb + tx * 4] = o;
        if (dotrans) {
            int ii = ty * 8 + i;
            tb[(tx * 4 + 0) * 129 + ii] = o.x;
            tb[(tx * 4 + 1) * 129 + ii] = o.y;
            tb[(tx * 4 + 2) * 129 + ii] = o.z;
            tb[(tx * 4 + 3) * 129 + ii] = o.w;
        }
    }
    if (dotrans) {
        __syncthreads();
        const int mloc = mb - batch0;
#pragma unroll
        for (int u = 0; u < 8; u++) {
            int idx = tid + u * 256;
            int row = idx >> 5;
            int q = idx & 31;
            const float* s = tb + row * 129 + 4 * q;
            float4 v = make_float4(s[0], s[1], s[2], s[3]);
            *(float4*)&pd[(long long)(jrow0 + row) * NPTS + mloc + 4 * q] = v;
        }
    }
}

// ---------------------------------------------------------------------------
// Phase B: exact top-16 per row, warp per row, per-lane top-2 tracking.
// ---------------------------------------------------------------------------
__global__ void topk_kernel(const float* __restrict__ pd, int* __restrict__ outidx) {
    extern __shared__ float rows[];
    const int warp = threadIdx.x >> 5, lane = threadIdx.x & 31;
    const long long row = (long long)blockIdx.x * 8 + warp;
    float* rb = rows + warp * 2048;
    const float4* src = (const float4*)(pd + row * NPTS);
#pragma unroll
    for (int i = 0; i < 16; i++)
        ((float4*)rb)[lane + i * 32] = src[lane + i * 32];
    __syncwarp();

    float bestv = -CUDART_INF_F, secondv = -CUDART_INF_F;
    int besti = 0x7fffffff, seci = -1;
#pragma unroll 8
    for (int s = 0; s < 64; s++) {
        float pv = rb[lane + 32 * s];
        int ix = lane + 32 * s;
        if (pv > bestv) {
            secondv = bestv; seci = besti;
            bestv = pv; besti = ix;
        } else if (pv > secondv) {
            secondv = pv; seci = ix;
        }
    }

    for (int t = 0; t < KNN; t++) {
        float wv = bestv; int wi = besti;
#pragma unroll
        for (int off = 16; off > 0; off >>= 1) {
            float ov = __shfl_xor_sync(0xffffffffu, wv, off);
            int oi = __shfl_xor_sync(0xffffffffu, wi, off);
            if (ov > wv || (ov == wv && oi < wi)) { wv = ov; wi = oi; }
        }
        if (lane == 0) outidx[row * KNN + t] = wi;
        if (besti == wi) {
            rb[wi] = -CUDART_INF_F;
            if (seci >= 0) {
                bestv = secondv; besti = seci;
                secondv = -CUDART_INF_F; seci = -1;
            } else {
                bestv = -CUDART_INF_F; secondv = -CUDART_INF_F;
                besti = 0x7fffffff; seci = -1;
#pragma unroll 8
                for (int s = 0; s < 64; s++) {
                    float pv = rb[lane + 32 * s];
                    int ix = lane + 32 * s;
                    if (pv > bestv) {
                        secondv = bestv; seci = besti;
                        bestv = pv; besti = ix;
                    } else if (pv > secondv) {
                        secondv = pv; seci = ix;
                    }
                }
            }
        }
    }
}

// ---------------------------------------------------------------------------
// SGEMM 128x64x16, 8x4 micro in f32x2, double-buffered, launch_bounds(256,2).
// dual: out = A @ [Wtop|Wbot]. accum: Co += (sequential, deterministic).
// BN+ReLU applied after accumulation when bg != null.
// ---------------------------------------------------------------------------
__global__ void __launch_bounds__(256, 2)
sgemm_kernel(const float* __restrict__ A, int lda,
             const float* __restrict__ W, int K, int D, int dual, int accum,
             float* __restrict__ Co, int ldc,
             const float* __restrict__ bg, const float* __restrict__ bb,
             const float* __restrict__ bm, const float* __restrict__ bvv) {
    __shared__ float As[2][16 * 264];
    __shared__ float Bs[2][16 * 68];
    const int mb = blockIdx.y * 128, nb = blockIdx.x * 64;
    const int tid = threadIdx.x;
    const int ty = tid >> 4, tx = tid & 15;
    u64 acc[8][2];
#pragma unroll
    for (int r = 0; r < 8; r++) { acc[r][0] = 0ull; acc[r][1] = 0ull; }
    float ra[8], rb[4];

#pragma unroll
    for (int u = 0; u < 8; u++) {
        int t = tid + u * 256; int m = t >> 4, k = t & 15;
        ra[u] = (k < K) ? A[(long long)(mb + m) * lda + k] : 0.f;
    }
#pragma unroll
    for (int u = 0; u < 4; u++) {
        int t = tid + u * 256; int k = t >> 6, n = t & 63;
        int gn = nb + n;
        float val = 0.f;
        if (k < K) {
            if (!dual) val = W[(long long)k * D + gn];
            else if (gn < D) val = W[(long long)k * D + gn];
            else val = W[(long long)(K + k) * D + gn - D];
        }
        rb[u] = val;
    }
#pragma unroll
    for (int u = 0; u < 8; u++) {
        int t = tid + u * 256;
        As[0][(t & 15) * 264 + 2 * (t >> 4)] = ra[u];
        As[0][(t & 15) * 264 + 2 * (t >> 4) + 1] = ra[u];
    }
#pragma unroll
    for (int u = 0; u < 4; u++) {
        int t = tid + u * 256;
        Bs[0][(t >> 6) * 68 + (t & 63)] = rb[u];
    }
    __syncthreads();

    int p = 0;
    for (int kt = 0; kt < K; kt += 16) {
        const bool more = (kt + 16 < K);
        if (more) {
#pragma unroll
            for (int u = 0; u < 8; u++) {
                int t = tid + u * 256; int m = t >> 4, k = kt + 16 + (t & 15);
                ra[u] = (k < K) ? A[(long long)(mb + m) * lda + k] : 0.f;
            }
#pragma unroll
            for (int u = 0; u < 4; u++) {
                int t = tid + u * 256; int k = kt + 16 + (t >> 6), n = t & 63;
                int gn = nb + n;
                float val = 0.f;
                if (k < K) {
                    if (!dual) val = W[(long long)k * D + gn];
                    else if (gn < D) val = W[(long long)k * D + gn];
                    else val = W[(long long)(K + k) * D + gn - D];
                }
                rb[u] = val;
            }
        }
        const float* ap = &As[p][ty * 16];
        const float* bp = &Bs[p][tx * 4];
#pragma unroll
        for (int k = 0; k < 16; k++) {
            ulonglong2 a01 = *(const ulonglong2*)(ap + k * 264);
            ulonglong2 a23 = *(const ulonglong2*)(ap + k * 264 + 4);
            ulonglong2 a45 = *(const ulonglong2*)(ap + k * 264 + 8);
            ulonglong2 a67 = *(const ulonglong2*)(ap + k * 264 + 12);
            ulonglong2 bq  = *(const ulonglong2*)(bp + k * 68);
            ffma2(acc[0][0], a01.x, bq.x); ffma2(acc[0][1], a01.x, bq.y);
            ffma2(acc[1][0], a01.y, bq.x); ffma2(acc[1][1], a01.y, bq.y);
            ffma2(acc[2][0], a23.x, bq.x); ffma2(acc[2][1], a23.x, bq.y);
            ffma2(acc[3][0], a23.y, bq.x); ffma2(acc[3][1], a23.y, bq.y);
            ffma2(acc[4][0], a45.x, bq.x); ffma2(acc[4][1], a45.x, bq.y);
            ffma2(acc[5][0], a45.y, bq.x); ffma2(acc[5][1], a45.y, bq.y);
            ffma2(acc[6][0], a67.x, bq.x); ffma2(acc[6][1], a67.x, bq.y);
            ffma2(acc[7][0], a67.y, bq.x); ffma2(acc[7][1], a67.y, bq.y);
        }
        if (more) {
            __syncthreads();
#pragma unroll
            for (int u = 0; u < 8; u++) {
                int t = tid + u * 256;
                As[p ^ 1][(t & 15) * 264 + 2 * (t >> 4)] = ra[u];
                As[p ^ 1][(t & 15) * 264 + 2 * (t >> 4) + 1] = ra[u];
            }
#pragma unroll
            for (int u = 0; u < 4; u++) {
                int t = tid + u * 256;
                Bs[p ^ 1][(t >> 6) * 68 + (t & 63)] = rb[u];
            }
            __syncthreads();
            p ^= 1;
        }
    }

    float s4[4], t4[4];
    if (bg) {
#pragma unroll
        for (int j = 0; j < 4; j++) {
            int n = nb + tx * 4 + j;
            s4[j] = bg[n] * rsqrtf(bvv[n] + BN_EPS);
            t4[j] = bb[n] - bm[n] * s4[j];
        }
    }
#pragma unroll
    for (int i = 0; i < 8; i++) {
        float2 lo = unpack2(acc[i][0]);
        float2 hi = unpack2(acc[i][1]);
        float o[4] = {lo.x, lo.y, hi.x, hi.y};
        float* cp = &Co[(long long)(mb + ty * 8 + i) * ldc + nb + tx * 4];
        if (accum) {
            float4 prev = *(float4*)cp;
            o[0] += prev.x; o[1] += prev.y; o[2] += prev.z; o[3] += prev.w;
        }
        if (bg) {
#pragma unroll
            for (int j = 0; j < 4; j++)
                o[j] = fmaxf(fmaf(o[j], s4[j], t4[j]), 0.f);
        }
        *(float4*)cp = make_float4(o[0], o[1], o[2], o[3]);
    }
}

// ---------------------------------------------------------------------------
// gather + BN + ReLU + max over k=16; fused next-stage sqnorm. Warp per row.
// ---------------------------------------------------------------------------
__global__ void gathermax_kernel(const float* __restrict__ ytb, const int* __restrict__ idx,
                                 int D,
                                 const float* __restrict__ g, const float* __restrict__ b,
                                 const float* __restrict__ m, const float* __restrict__ vv,
                                 float* __restrict__ out, float* __restrict__ sqout) {
    const int warp = (blockIdx.x * blockDim.x + threadIdx.x) >> 5;
    const int lane = threadIdx.x & 31;
    if (warp >= NROWS) return;
    const int row = warp;
    const int base = row & ~(NPTS - 1);
    const int myid = idx[(long long)row * KNN + (lane & 15)];
    const float* top = ytb + (long long)row * 2 * D;
    float ss = 0.f;
    for (int c0 = 0; c0 < D; c0 += 64) {
        const int d = c0 + lane * 2;
        float2 g2 = *(const float2*)&g[d];
        float2 v2 = *(const float2*)&vv[d];
        float2 b2 = *(const float2*)&b[d];
        float2 m2 = *(const float2*)&m[d];
        float sx = g2.x * rsqrtf(v2.x + BN_EPS), txx = b2.x - m2.x * sx;
        float sy = g2.y * rsqrtf(v2.y + BN_EPS), tyy = b2.y - m2.y * sy;
        float2 tp = *(const float2*)&top[d];
        float bx = -CUDART_INF_F, by = -CUDART_INF_F;
#pragma unroll
        for (int k = 0; k < KNN; k++) {
            int sk = __shfl_sync(0xffffffffu, myid, k, 16);
            float2 yb = *(const float2*)&ytb[(long long)(base + sk) * 2 * D + D + d];
            bx = fmaxf(bx, fmaf(tp.x + yb.x, sx, txx));
            by = fmaxf(by, fmaf(tp.y + yb.y, sy, tyy));
        }
        bx = fmaxf(bx, 0.f); by = fmaxf(by, 0.f);
        *(float2*)&out[(long long)row * 512 + d] = make_float2(bx, by);
        ss += bx * bx + by * by;
    }
#pragma unroll
    for (int off = 16; off > 0; off >>= 1) ss += __shfl_down_sync(0xffffffffu, ss, off);
    if (lane == 0) sqout[row] = ss;
}

// ---------------------------------------------------------------------------
extern "C" void kernel_launch(void* const* d_in, const int* in_sizes, int n_in,
                              void* d_out, int out_size) {
    const float* x = (const float*)d_in[0];
    const float *W[5], *gg[5], *bb[5], *mm[5], *vv[5];
    for (int i = 0; i < 5; i++) {
        W[i]  = (const float*)d_in[1 + 5 * i];
        gg[i] = (const float*)d_in[2 + 5 * i];
        bb[i] = (const float*)d_in[3 + 5 * i];
        mm[i] = (const float*)d_in[4 + 5 * i];
        vv[i] = (const float*)d_in[5 + 5 * i];
    }
    float *xcat, *ytb, *sqp, *pdp; int* idxp;
    cudaGetSymbolAddress((void**)&xcat, g_xcat);
    cudaGetSymbolAddress((void**)&ytb, g_ytb);
    cudaGetSymbolAddress((void**)&sqp, g_sq);
    cudaGetSymbolAddress((void**)&idxp, g_idx);
    cudaGetSymbolAddress((void**)&pdp, g_pd);

    // one-time setup: smem attr + side stream + fork/join events
    static cudaStream_t side = nullptr;
    static cudaEvent_t evF[5], evJ[4], evEnd;
    if (!side) {
        cudaFuncSetAttribute(topk_kernel, cudaFuncAttributeMaxDynamicSharedMemorySize,
                             8 * 2048 * 4);
        cudaStreamCreateWithFlags(&side, cudaStreamNonBlocking);
        for (int i = 0; i < 5; i++)
            cudaEventCreateWithFlags(&evF[i], cudaEventDisableTiming);
        for (int i = 0; i < 4; i++)
            cudaEventCreateWithFlags(&evJ[i], cudaEventDisableTiming);
        cudaEventCreateWithFlags(&evEnd, cudaEventDisableTiming);
    }

    const int Cs[4] = {3, 64, 64, 128};
    const int Ds[4] = {64, 64, 128, 256};
    const int Coff[4] = {0, 64, 128, 256};
    float* outfin = (float*)d_out;

    sqnorm_kernel<<<NROWS / 256, 256>>>(x, 3, 3, sqp);

    const float* in = x;
    int lda = 3;
    for (int s = 0; s < 4; s++) {
        const int C = Cs[s], D = Ds[s];
        // fork: side gets this stage's dual sgemm (+ prev stage's final-partial)
        cudaEventRecord(evF[s], 0);
        cudaStreamWaitEvent(side, evF[s], 0);
        sgemm_kernel<<<dim3(2 * D / 64, NROWS / 128), 256, 0, side>>>(
            in, lda, W[s], C, D, 1, 0, ytb, 2 * D,
            nullptr, nullptr, nullptr, nullptr);
        cudaEventRecord(evJ[s], side);
        if (s > 0) {
            // final-GEMM partial for stage s-1 (input xcat cols ready)
            const int ps = s - 1;
            const int pc = Coff[ps], pk = Ds[ps];
            sgemm_kernel<<<dim3(512 / 64, NROWS / 128), 256, 0, side>>>(
                xcat + pc, 512, W[4] + (long long)pc * 512, pk, 512, 0, ps > 0,
                outfin, 512, nullptr, nullptr, nullptr, nullptr);
        }
        // main: pdgemm + topk, then join and gathermax
        pdgemm_kernel<<<dim3(NPTS / 64, NROWS / 128), 256>>>(in, lda, C, sqp, pdp);
        topk_kernel<<<NROWS / 8, 256, 8 * 2048 * 4>>>(pdp, idxp);
        cudaStreamWaitEvent(0, evJ[s], 0);
        float* outp = xcat + Coff[s];
        gathermax_kernel<<<NROWS / 8, 256>>>(ytb, idxp, D, gg[s], bb[s], mm[s], vv[s],
                                             outp, sqp);
        in = outp; lda = 512;
    }
    // last final-GEMM partial (x4 slice): accumulate + BN + ReLU
    cudaEventRecord(evF[4], 0);
    cudaStreamWaitEvent(side, evF[4], 0);
    sgemm_kernel<<<dim3(512 / 64, NROWS / 128), 256, 0, side>>>(
        xcat + 256, 512, W[4] + (long long)256 * 512, 256, 512, 0, 1,
        outfin, 512, gg[4], bb[4], mm[4], vv[4]);
    cudaEventRecord(evEnd, side);
    cudaStreamWaitEvent(0, evEnd, 0);
}